// round 11
// baseline (speedup 1.0000x reference)
#include <cuda_runtime.h>
#include <cstdint>

#define S_  512      // B*T segments
#define P_  1024     // points per segment
#define D3  256
#define NPTS (S_ * P_)

// ---------------- global scratch ----------------
__device__ uint32_t g_h2[(size_t)NPTS * 128];  // masked h2 as tf32 bits (256 MB)
__device__ uint32_t g_w3t[256 * 128];          // W3 top, tf32, [n][k]
__device__ uint32_t g_w4t[256 * 256];          // W4, tf32, [n][k]
__device__ float g_pool[S_ * 128];
__device__ float g_c[S_ * D3];
__device__ float g_feat[S_ * D3];
__device__ int   g_valid[S_];

__device__ __forceinline__ void atomicMaxF_nonneg(float* addr, float v) {
    atomicMax((int*)addr, __float_as_int(v));   // valid for non-negative floats
}
__device__ __forceinline__ uint32_t f2tf32(float x) {
    uint32_t r; asm("cvt.rna.tf32.f32 %0, %1;" : "=r"(r) : "f"(x)); return r;
}
__device__ __forceinline__ void mma_tf32(float d[4], const uint32_t a[4], const uint32_t b[2]) {
    asm volatile(
        "mma.sync.aligned.m16n8k8.row.col.f32.tf32.tf32.f32 "
        "{%0,%1,%2,%3}, {%4,%5,%6,%7}, {%8,%9}, {%0,%1,%2,%3};\n"
        : "+f"(d[0]), "+f"(d[1]), "+f"(d[2]), "+f"(d[3])
        : "r"(a[0]), "r"(a[1]), "r"(a[2]), "r"(a[3]), "r"(b[0]), "r"(b[1]));
}
__device__ __forceinline__ void ldsm4(uint32_t d[4], uint32_t addr) {
    asm volatile("ldmatrix.sync.aligned.m8n8.x4.shared.b16 {%0,%1,%2,%3}, [%4];"
                 : "=r"(d[0]), "=r"(d[1]), "=r"(d[2]), "=r"(d[3]) : "r"(addr));
}
__device__ __forceinline__ void cp_async16(uint32_t saddr, const void* gaddr) {
    asm volatile("cp.async.cg.shared.global [%0], [%1], 16;"
                 :: "r"(saddr), "l"(gaddr) : "memory");
}
__device__ __forceinline__ void cp_commit() {
    asm volatile("cp.async.commit_group;" ::: "memory");
}

// ============================= kZ: zero the accumulators =============================
__global__ void kZ() {
    int i = blockIdx.x * 256 + threadIdx.x;     // grid 512 -> i < 131072
    g_feat[i] = 0.f;
    if (i < S_ * 128) g_pool[i] = 0.f;
    if (i < S_) g_valid[i] = 0;
}

// =========== kP: pack W (K x N f32 row-major) -> dst [n][k] tf32 words ==============
__global__ void kP(const float* __restrict__ W, uint32_t* __restrict__ dst, int K, int N) {
    int i = blockIdx.x * 256 + threadIdx.x;
    if (i >= K * N) return;
    int n = i % N, k = i / N;
    dst[n * K + k] = f2tf32(W[k * N + n]);
}

// =====================================================================================
// Kernel A (tf32 MMA): 128 points/CTA, grid 4096, 256 thr.
// h2 epilogue stages fragments in smem (dead xs/w1s/h1s region) and writes g_h2 with
// fully-coalesced row-major uint4 stores (two passes: mi=0, mi=1).
#define A_XS  0        // [128][36]           (stage buffer [64][132] overlays 0..8448)
#define A_W1  4608     // [32][72]
#define A_H1  6912     // [128][68]
#define A_W2  15616    // [64][136]
#define A_B1  24320    // 64
#define A_B2  24384    // 128
#define A_MS  24512    // 128 (int)
#define A_VF  24640    // 1
#define A_SMW 24641
// =====================================================================================
__global__ void __launch_bounds__(256, 2)
kA(const float* __restrict__ x, const int* __restrict__ mask,
   const float* __restrict__ W1, const float* __restrict__ b1,
   const float* __restrict__ W2, const float* __restrict__ b2)
{
    extern __shared__ uint32_t smw[];
    uint32_t* xs  = smw + A_XS;
    uint32_t* w1s = smw + A_W1;
    uint32_t* h1s = smw + A_H1;
    uint32_t* w2s = smw + A_W2;
    uint32_t* stg = smw;                // [64][132] stage (valid after h2 mma)
    float* b1s = (float*)(smw + A_B1);
    float* b2s = (float*)(smw + A_B2);
    int*   ms  = (int*)(smw + A_MS);
    int*   vf  = (int*)(smw + A_VF);

    const int t = threadIdx.x;
    const int lane = t & 31, wid = t >> 5;
    const int g = lane >> 2, tg = lane & 3;
    const int m0 = blockIdx.x * 128;
    const int s  = m0 >> 10;

    {
        const int r = t >> 1, c16 = (t & 1) * 16;
        const float* gx = x + (size_t)(m0 + r) * 32 + c16;
        #pragma unroll
        for (int q = 0; q < 4; q++) {
            float4 v = *(const float4*)(gx + 4 * q);
            *(uint4*)(xs + r * 36 + c16 + 4 * q) =
                make_uint4(f2tf32(v.x), f2tf32(v.y), f2tf32(v.z), f2tf32(v.w));
        }
    }
    for (int i = t; i < 2048; i += 256) w1s[(i >> 6) * 72 + (i & 63)] = f2tf32(W1[i]);
    for (int i = t; i < 8192; i += 256) w2s[(i >> 7) * 136 + (i & 127)] = f2tf32(W2[i]);
    if (t < 64)  b1s[t] = b1[t];
    if (t < 128) b2s[t] = b2[t];
    if (t == 0)  *vf = 0;
    if (t < 128) {
        int mv = (mask[m0 + t] != 0);
        ms[t] = mv;
        if (mv) atomicOr(vf, 1);
    }
    __syncthreads();

    // h1 = relu(x@W1+b1): M128,N64,K32; warp tile 16x64
    {
        const int wm1 = wid * 16;
        float acc[8][4];
        #pragma unroll
        for (int ni = 0; ni < 8; ni++) {
            float ba = b1s[ni * 8 + 2 * tg], bb = b1s[ni * 8 + 2 * tg + 1];
            acc[ni][0] = ba; acc[ni][1] = bb; acc[ni][2] = ba; acc[ni][3] = bb;
        }
        #pragma unroll
        for (int k0 = 0; k0 < 32; k0 += 8) {
            uint32_t af[4];
            const int r = wm1 + g;
            af[0] = xs[r * 36 + k0 + tg];
            af[1] = xs[(r + 8) * 36 + k0 + tg];
            af[2] = xs[r * 36 + k0 + tg + 4];
            af[3] = xs[(r + 8) * 36 + k0 + tg + 4];
            uint32_t bf[8][2];
            #pragma unroll
            for (int ni = 0; ni < 8; ni++) {
                bf[ni][0] = w1s[(k0 + tg) * 72 + ni * 8 + g];
                bf[ni][1] = w1s[(k0 + tg + 4) * 72 + ni * 8 + g];
            }
            #pragma unroll
            for (int ni = 0; ni < 8; ni++) mma_tf32(acc[ni], af, bf[ni]);
        }
        const int r = wm1 + g;
        #pragma unroll
        for (int ni = 0; ni < 8; ni++) {
            int c0 = ni * 8 + 2 * tg;
            *(uint2*)(h1s + r * 68 + c0) = make_uint2(
                f2tf32(fmaxf(acc[ni][0], 0.f)), f2tf32(fmaxf(acc[ni][1], 0.f)));
            *(uint2*)(h1s + (r + 8) * 68 + c0) = make_uint2(
                f2tf32(fmaxf(acc[ni][2], 0.f)), f2tf32(fmaxf(acc[ni][3], 0.f)));
        }
    }
    __syncthreads();

    // h2 = relu(h1@W2+b2) mask: M128,N128,K64; warp tile 32x64
    {
        const int wm = (wid & 3) * 32, wn = (wid >> 2) * 64;
        float acc[2][8][4];
        #pragma unroll
        for (int mi = 0; mi < 2; mi++)
            #pragma unroll
            for (int ni = 0; ni < 8; ni++) {
                float ba = b2s[wn + ni * 8 + 2 * tg], bb = b2s[wn + ni * 8 + 2 * tg + 1];
                acc[mi][ni][0] = ba; acc[mi][ni][1] = bb;
                acc[mi][ni][2] = ba; acc[mi][ni][3] = bb;
            }
        #pragma unroll
        for (int k0 = 0; k0 < 64; k0 += 8) {
            uint32_t af[2][4];
            #pragma unroll
            for (int mi = 0; mi < 2; mi++) {
                const int r = wm + mi * 16 + g;
                af[mi][0] = h1s[r * 68 + k0 + tg];
                af[mi][1] = h1s[(r + 8) * 68 + k0 + tg];
                af[mi][2] = h1s[r * 68 + k0 + tg + 4];
                af[mi][3] = h1s[(r + 8) * 68 + k0 + tg + 4];
            }
            uint32_t bf[8][2];
            #pragma unroll
            for (int ni = 0; ni < 8; ni++) {
                bf[ni][0] = w2s[(k0 + tg) * 136 + wn + ni * 8 + g];
                bf[ni][1] = w2s[(k0 + tg + 4) * 136 + wn + ni * 8 + g];
            }
            #pragma unroll
            for (int mi = 0; mi < 2; mi++)
                #pragma unroll
                for (int ni = 0; ni < 8; ni++) mma_tf32(acc[mi][ni], af[mi], bf[ni]);
        }
        __syncthreads();     // all warps done reading h1s/w2s -> stage region free

        float pmax[8][2];
        #pragma unroll
        for (int ni = 0; ni < 8; ni++) { pmax[ni][0] = 0.f; pmax[ni][1] = 0.f; }

        // ---- two staged passes: fragment->smem, then coalesced smem->gmem ----
        #pragma unroll
        for (int mi = 0; mi < 2; mi++) {
            const int r = wm + mi * 16 + g;              // global rows r, r+8
            const int k0v = ms[r], k1v = ms[r + 8];
            const int sr0 = (wm >> 5) * 16 + g;          // stage rows sr0, sr0+8
            #pragma unroll
            for (int ni = 0; ni < 8; ni++) {
                int c0 = wn + ni * 8 + 2 * tg;
                float v0 = k0v ? fmaxf(acc[mi][ni][0], 0.f) : 0.f;
                float v1 = k0v ? fmaxf(acc[mi][ni][1], 0.f) : 0.f;
                float v2 = k1v ? fmaxf(acc[mi][ni][2], 0.f) : 0.f;
                float v3 = k1v ? fmaxf(acc[mi][ni][3], 0.f) : 0.f;
                pmax[ni][0] = fmaxf(pmax[ni][0], fmaxf(v0, v2));
                pmax[ni][1] = fmaxf(pmax[ni][1], fmaxf(v1, v3));
                *(uint2*)(stg + sr0 * 132 + c0)       = make_uint2(f2tf32(v0), f2tf32(v1));
                *(uint2*)(stg + (sr0 + 8) * 132 + c0) = make_uint2(f2tf32(v2), f2tf32(v3));
            }
            __syncthreads();     // stage full
            #pragma unroll
            for (int j = 0; j < 8; j++) {    // 64 rows x 32 uint4, coalesced
                int i = t + j * 256;
                int srow = i >> 5, off = (i & 31) * 4;
                int grow = (srow >> 4) * 32 + mi * 16 + (srow & 15);
                uint4 v = *(const uint4*)(stg + srow * 132 + off);
                *(uint4*)(g_h2 + (size_t)(m0 + grow) * 128 + off) = v;
            }
            __syncthreads();     // stage reusable
        }

        // pool reduce: shfl-max across g lanes, then one global atomic per col
        #pragma unroll
        for (int ni = 0; ni < 8; ni++) {
            float mx0 = pmax[ni][0], mx1 = pmax[ni][1];
            #pragma unroll
            for (int off = 4; off < 32; off <<= 1) {
                mx0 = fmaxf(mx0, __shfl_xor_sync(0xffffffffu, mx0, off));
                mx1 = fmaxf(mx1, __shfl_xor_sync(0xffffffffu, mx1, off));
            }
            if (g == 0) {
                atomicMaxF_nonneg(&g_pool[s * 128 + wn + ni * 8 + 2 * tg], mx0);
                atomicMaxF_nonneg(&g_pool[s * 128 + wn + ni * 8 + 2 * tg + 1], mx1);
            }
        }
    }
    if (t == 0 && *vf) atomicOr(&g_valid[s], 1);
}

// ============================= kA2: c = b3 + pool @ W3_bot (fp32) ====================
__global__ void __launch_bounds__(256, 4)
kA2(const float* __restrict__ W3, const float* __restrict__ b3)
{
    __shared__ float ps[128];
    const int t = threadIdx.x, s = blockIdx.x;
    if (t < 128) ps[t] = g_pool[s * 128 + t];
    __syncthreads();
    float acc = b3[t];
    #pragma unroll 8
    for (int k = 0; k < 128; k++)
        acc += ps[k] * W3[(size_t)(128 + k) * D3 + t];
    g_c[s * D3 + t] = acc;
}

// =====================================================================================
// kBC (tf32, ldmatrix, cp.async): 256 threads, warp tiles 64x64 (2m x 4n warps).
// phase1: h3 = relu(h2 @ W3top^T + c), staged entry loads (4 k-stage cp.async groups).
// phase2: acc = h3 @ W4, K=256 via 8 cp.async double-buffered k32 chunks.
// smem words:
#define BC_R1   0        // 18432: h2s [128][132] (phase1) / W4 bufs 2x[256][36] (phase2)
#define BC_R2   18432    // 33792: w3s [256][132] (phase1) / h3s [128][260] (phase2)
#define BC_CV   52224    // 256
#define BC_B4   52480    // 256
#define BC_CM   52736    // 256
#define BC_MS   52992    // 128 (int)
#define BC_SMW  53120    // -> 212480 B
// =====================================================================================
__global__ void __launch_bounds__(256, 1)
kBC(const float* __restrict__ b4, const int* __restrict__ mask)
{
    extern __shared__ uint32_t smw[];
    uint32_t* h3s = smw + BC_R2;            // overlays w3s after phase1
    float* cv   = (float*)(smw + BC_CV);
    float* b4s  = (float*)(smw + BC_B4);
    float* cmax = (float*)(smw + BC_CM);
    int*   ms   = (int*)(smw + BC_MS);

    const int t = threadIdx.x;
    const int lane = t & 31, wid = t >> 5;
    const int g = lane >> 2, tg = lane & 3;
    const int wm = (wid & 1) * 64;          // 2 m-groups of 64
    const int wn = (wid >> 1) * 64;         // 4 n-groups of 64
    const int m0 = blockIdx.x * 128;
    const int s  = m0 >> 10;

    const uint32_t smb = (uint32_t)__cvta_generic_to_shared(smw);
    const uint32_t r1b = smb;                    // bytes
    const uint32_t r2b = smb + BC_R2 * 4;
    // ldmatrix lane offsets (bytes)
    const int laneA = lane & 15, kselA = (lane >> 4) * 4;
    const int laneB = ((lane >> 4) << 3) + (lane & 7), kselB = ((lane >> 3) & 1) * 4;
    const uint32_t pA1 = (uint32_t)(laneA * 132 + kselA) * 4;
    const uint32_t pB1 = (uint32_t)(laneB * 132 + kselB) * 4;
    const uint32_t pA2 = (uint32_t)(laneA * 260 + kselA) * 4;
    const uint32_t pB2 = (uint32_t)(laneB * 36  + kselB) * 4;

    // ---- staged cp.async load: 4 k-stages of (h2 32 words/row + w3 32 words/row) ----
    #pragma unroll
    for (int st = 0; st < 4; st++) {
        #pragma unroll
        for (int j = 0; j < 4; j++) {               // h2: 128 rows x 8 uint4
            int i = t + j * 256;
            int row = i >> 3, off = (i & 7) * 4;
            cp_async16(r1b + (uint32_t)((row * 132 + st * 32 + off) * 4),
                       g_h2 + (size_t)(m0 + row) * 128 + st * 32 + off);
        }
        #pragma unroll
        for (int j = 0; j < 8; j++) {               // w3: 256 rows x 8 uint4
            int i = t + j * 256;
            int n = i >> 3, off = (i & 7) * 4;
            cp_async16(r2b + (uint32_t)((n * 132 + st * 32 + off) * 4),
                       g_w3t + n * 128 + st * 32 + off);
        }
        cp_commit();
    }

    cv[t] = g_c[s * D3 + t]; b4s[t] = b4[t]; cmax[t] = 0.f;
    if (t < 128) ms[t] = (mask[m0 + t] != 0);

    // ---- phase1: 4 stages x 4 k8-steps, 32 mma each ----
    float acc[4][8][4];
    #pragma unroll
    for (int mi = 0; mi < 4; mi++)
        #pragma unroll
        for (int ni = 0; ni < 8; ni++)
            #pragma unroll
            for (int q = 0; q < 4; q++) acc[mi][ni][q] = 0.f;

    #pragma unroll
    for (int stg = 0; stg < 4; stg++) {
        if      (stg == 0) asm volatile("cp.async.wait_group 3;" ::: "memory");
        else if (stg == 1) asm volatile("cp.async.wait_group 2;" ::: "memory");
        else if (stg == 2) asm volatile("cp.async.wait_group 1;" ::: "memory");
        else               asm volatile("cp.async.wait_group 0;" ::: "memory");
        __syncthreads();
        #pragma unroll
        for (int kss = 0; kss < 4; kss++) {
            const int k0 = stg * 32 + kss * 8;
            uint32_t af[4][4], bf[4][4];
            #pragma unroll
            for (int mi = 0; mi < 4; mi++)
                ldsm4(af[mi], r1b + (uint32_t)(((wm + mi * 16) * 132 + k0) * 4) + pA1);
            #pragma unroll
            for (int p = 0; p < 4; p++)
                ldsm4(bf[p], r2b + (uint32_t)(((wn + p * 16) * 132 + k0) * 4) + pB1);
            #pragma unroll
            for (int mi = 0; mi < 4; mi++)
                #pragma unroll
                for (int ni = 0; ni < 8; ni++)
                    mma_tf32(acc[mi][ni], af[mi], &bf[ni >> 1][(ni & 1) * 2]);
        }
    }
    __syncthreads();   // all warps done reading h2s/w3s

    // issue W4 chunks 0,1 via cp.async into r1 bufs (h2s region is dead)
    {
        #pragma unroll
        for (int j = 0; j < 8; j++) {
            int i = t + j * 256;
            int n = i >> 3, q4 = (i & 7) * 4;
            cp_async16(r1b + (uint32_t)((n * 36 + q4) * 4), g_w4t + n * 256 + q4);
        }
        cp_commit();
        #pragma unroll
        for (int j = 0; j < 8; j++) {
            int i = t + j * 256;
            int n = i >> 3, q4 = (i & 7) * 4;
            cp_async16(r1b + (uint32_t)((9216 + n * 36 + q4) * 4), g_w4t + n * 256 + 32 + q4);
        }
        cp_commit();
    }

    // epilogue1: h3 = relu(acc + c) (tf32) overwrites w3s region, [m][k] stride 260
    #pragma unroll
    for (int mi = 0; mi < 4; mi++) {
        const int R = wm + mi * 16;
        #pragma unroll
        for (int ni = 0; ni < 8; ni++) {
            int c0 = wn + ni * 8 + 2 * tg;
            float ca = cv[c0], cb = cv[c0 + 1];
            *(uint2*)(h3s + (R + g) * 260 + c0) = make_uint2(
                f2tf32(fmaxf(acc[mi][ni][0] + ca, 0.f)),
                f2tf32(fmaxf(acc[mi][ni][1] + cb, 0.f)));
            *(uint2*)(h3s + (R + 8 + g) * 260 + c0) = make_uint2(
                f2tf32(fmaxf(acc[mi][ni][2] + ca, 0.f)),
                f2tf32(fmaxf(acc[mi][ni][3] + cb, 0.f)));
        }
    }
    __syncthreads();   // h3 visible

    // ---- phase2: 8 chunks of k=32, cp.async double-buffered ----
    float acc2[4][8][4];
    #pragma unroll
    for (int mi = 0; mi < 4; mi++)
        #pragma unroll
        for (int ni = 0; ni < 8; ni++) {
            float ba = b4s[wn + ni * 8 + 2 * tg], bb = b4s[wn + ni * 8 + 2 * tg + 1];
            acc2[mi][ni][0] = ba; acc2[mi][ni][1] = bb;
            acc2[mi][ni][2] = ba; acc2[mi][ni][3] = bb;
        }
    #pragma unroll 1
    for (int ch = 0; ch < 8; ++ch) {
        if (ch == 7) asm volatile("cp.async.wait_group 0;" ::: "memory");
        else         asm volatile("cp.async.wait_group 1;" ::: "memory");
        __syncthreads();
        const uint32_t bufb = r1b + (uint32_t)((ch & 1) * 9216 * 4);
        #pragma unroll
        for (int ks = 0; ks < 4; ks++) {
            const int k0 = ks * 8;
            uint32_t af[4][4], bf[4][4];
            #pragma unroll
            for (int mi = 0; mi < 4; mi++)
                ldsm4(af[mi], r2b + (uint32_t)(((wm + mi * 16) * 260 + ch * 32 + k0) * 4) + pA2);
            #pragma unroll
            for (int p = 0; p < 4; p++)
                ldsm4(bf[p], bufb + (uint32_t)(((wn + p * 16) * 36 + k0) * 4) + pB2);
            #pragma unroll
            for (int mi = 0; mi < 4; mi++)
                #pragma unroll
                for (int ni = 0; ni < 8; ni++)
                    mma_tf32(acc2[mi][ni], af[mi], &bf[ni >> 1][(ni & 1) * 2]);
        }
        if (ch < 6) {
            __syncthreads();   // all warps done reading buf[ch&1]
            #pragma unroll
            for (int j = 0; j < 8; j++) {
                int i = t + j * 256;
                int n = i >> 3, q4 = (i & 7) * 4;
                cp_async16(bufb + (uint32_t)((n * 36 + q4) * 4),
                           g_w4t + n * 256 + (ch + 2) * 32 + q4);
            }
            cp_commit();
        }
    }

    // ---- final epilogue: relu (b4 in acc), mask rows, col max ----
    #pragma unroll
    for (int ni = 0; ni < 8; ni++) {
        int c0 = wn + ni * 8 + 2 * tg;
        float mx0 = 0.f, mx1 = 0.f;
        #pragma unroll
        for (int mi = 0; mi < 4; mi++) {
            const int R = wm + mi * 16;
            const int k0v = ms[R + g], k1v = ms[R + 8 + g];
            float v0 = fmaxf(acc2[mi][ni][0], 0.f);
            float v1 = fmaxf(acc2[mi][ni][1], 0.f);
            float v2 = fmaxf(acc2[mi][ni][2], 0.f);
            float v3 = fmaxf(acc2[mi][ni][3], 0.f);
            if (k0v) { mx0 = fmaxf(mx0, v0); mx1 = fmaxf(mx1, v1); }
            if (k1v) { mx0 = fmaxf(mx0, v2); mx1 = fmaxf(mx1, v3); }
        }
        atomicMaxF_nonneg(&cmax[c0], mx0);
        atomicMaxF_nonneg(&cmax[c0 + 1], mx1);
    }
    __syncthreads();
    atomicMax((int*)&g_feat[s * D3 + t], __float_as_int(cmax[t]));
}

// ============ kD: out MLP, 8 segments/CTA, weights read once per CTA =================
__global__ void __launch_bounds__(256, 2)
kD(const float* __restrict__ Wo1, const float* __restrict__ bo1,
   const float* __restrict__ Wo2, const float* __restrict__ bo2,
   float* __restrict__ out)
{
    __shared__ float fs[8][256], t1[8][256];
    __shared__ int vld[8];
    const int t = threadIdx.x, s0 = blockIdx.x * 8;
    for (int i = t; i < 8 * 256; i += 256)
        fs[i >> 8][i & 255] = g_feat[(s0 + (i >> 8)) * 256 + (i & 255)];
    if (t < 8) vld[t] = g_valid[s0 + t];
    __syncthreads();
    float a[8];
    #pragma unroll
    for (int e = 0; e < 8; e++) a[e] = bo1[t];
    for (int k = 0; k < 256; k += 4) {
        #pragma unroll
        for (int kk = 0; kk < 4; kk++) {
            float w = Wo1[(k + kk) * 256 + t];
            #pragma unroll
            for (int e = 0; e < 8; e++) a[e] += fs[e][k + kk] * w;
        }
    }
    #pragma unroll
    for (int e = 0; e < 8; e++) t1[e][t] = fmaxf(a[e], 0.f);
    __syncthreads();
    #pragma unroll
    for (int e = 0; e < 8; e++) a[e] = bo2[t];
    for (int k = 0; k < 256; k += 4) {
        #pragma unroll
        for (int kk = 0; kk < 4; kk++) {
            float w = Wo2[(k + kk) * 256 + t];
            #pragma unroll
            for (int e = 0; e < 8; e++) a[e] += t1[e][k + kk] * w;
        }
    }
    #pragma unroll
    for (int e = 0; e < 8; e++)
        out[(s0 + e) * 256 + t] = vld[e] ? a[e] : 0.f;
}

// =====================================================================================
extern "C" void kernel_launch(void* const* d_in, const int* in_sizes, int n_in,
                              void* d_out, int out_size)
{
    (void)in_sizes; (void)n_in; (void)out_size;
    const float* x   = (const float*)d_in[0];
    const int*   msk = (const int*)  d_in[1];
    const float* W1  = (const float*)d_in[2];
    const float* b1  = (const float*)d_in[3];
    const float* W2  = (const float*)d_in[4];
    const float* b2  = (const float*)d_in[5];
    const float* W3  = (const float*)d_in[6];
    const float* b3  = (const float*)d_in[7];
    const float* W4  = (const float*)d_in[8];
    const float* b4  = (const float*)d_in[9];
    const float* Wo1 = (const float*)d_in[10];
    const float* bo1 = (const float*)d_in[11];
    const float* Wo2 = (const float*)d_in[12];
    const float* bo2 = (const float*)d_in[13];
    float* out = (float*)d_out;

    uint32_t *w3t, *w4t;
    cudaGetSymbolAddress((void**)&w3t, g_w3t);
    cudaGetSymbolAddress((void**)&w4t, g_w4t);

    const size_t smA  = (size_t)A_SMW * 4;    //  98.6 KB
    const size_t smBC = (size_t)BC_SMW * 4;   // 212.5 KB

    cudaFuncSetAttribute(kA,  cudaFuncAttributeMaxDynamicSharedMemorySize, (int)smA);
    cudaFuncSetAttribute(kBC, cudaFuncAttributeMaxDynamicSharedMemorySize, (int)smBC);

    kZ<<<S_, 256>>>();
    kP<<<128, 256>>>(W3, w3t, 128, 256);   // W3 top half -> [n][k]
    kP<<<256, 256>>>(W4, w4t, 256, 256);   // W4 -> [n][k]
    kA <<<NPTS / 128, 256, smA>>>(x, msk, W1, b1, W2, b2);
    kA2<<<S_, 256>>>(W3, b3);
    kBC<<<NPTS / 128, 256, smBC>>>(b4, msk);
    kD <<<64, 256>>>(Wo1, bo1, Wo2, bo2, out);
}

// round 15
// speedup vs baseline: 1.6429x; 1.6429x over previous
#include <cuda_runtime.h>
#include <cstdint>

#define S_  512      // B*T segments
#define P_  1024     // points per segment
#define D3  256
#define NPTS (S_ * P_)

// ---------------- global scratch ----------------
__device__ uint32_t g_h2p[(size_t)NPTS * 64];  // masked h2, packed fp16 pairs (128 MB)
__device__ uint32_t g_w1p[64 * 16];            // W1 packed [n=64][kp=16]
__device__ uint32_t g_w2p[128 * 32];           // W2 packed [n=128][kp=32]
__device__ uint32_t g_w3p[256 * 64];           // W3 top packed [n=256][kp=64]
__device__ uint32_t g_w4p[256 * 128];          // W4 packed [n=256][kp=128]
__device__ float g_pool[S_ * 128];
__device__ float g_c[S_ * D3];
__device__ float g_feat[S_ * D3];
__device__ int   g_valid[S_];

__device__ __forceinline__ void atomicMaxF_nonneg(float* addr, float v) {
    atomicMax((int*)addr, __float_as_int(v));   // valid for non-negative floats
}
__device__ __forceinline__ uint32_t packh(float lo, float hi) {
    uint32_t r; asm("cvt.rn.f16x2.f32 %0, %1, %2;" : "=r"(r) : "f"(hi), "f"(lo)); return r;
}
__device__ __forceinline__ void mma_f16(float d[4], const uint32_t a[4], const uint32_t b[2]) {
    asm volatile(
        "mma.sync.aligned.m16n8k16.row.col.f32.f16.f16.f32 "
        "{%0,%1,%2,%3}, {%4,%5,%6,%7}, {%8,%9}, {%0,%1,%2,%3};\n"
        : "+f"(d[0]), "+f"(d[1]), "+f"(d[2]), "+f"(d[3])
        : "r"(a[0]), "r"(a[1]), "r"(a[2]), "r"(a[3]), "r"(b[0]), "r"(b[1]));
}

// ============================= kZ: zero the accumulators =============================
__global__ void kZ() {
    int i = blockIdx.x * 256 + threadIdx.x;     // grid 512 -> i < 131072
    g_feat[i] = 0.f;
    if (i < S_ * 128) g_pool[i] = 0.f;
    if (i < S_) g_valid[i] = 0;
}

// ============ kP: pack W (K x N f32, row-major) -> dst[n][kp] fp16 pairs ============
__global__ void kP(const float* __restrict__ W, uint32_t* __restrict__ dst, int K, int N) {
    int i = blockIdx.x * 256 + threadIdx.x;
    int total = (K / 2) * N;
    if (i >= total) return;
    int n = i % N, kp = i / N;
    dst[n * (K / 2) + kp] = packh(W[(2 * kp) * N + n], W[(2 * kp + 1) * N + n]);
}

// =====================================================================================
// Kernel A (fp16 MMA): 128 points/CTA, grid 4096, 256 threads.
//   x -> h1(64) -> h2(128) relu+mask, store packed fp16 pairs to g_h2p,
//   col-max -> atomicMax g_pool, valid -> atomicOr g_valid.
//   h1 warp tile 32x32 (full N=64 across 2 n-groups); h2 warp tile 32x64 (full N=128).
// smem word offsets:
#define A_XS  0        // [128][20]  x pairs (kp=16 + 4 pad)
#define A_W1  2560     // [64][20]
#define A_H1  3840     // [128][36]  h1 pairs (kp=32 + 4)
#define A_W2  8448     // [128][36]
#define A_B1  13056    // 64
#define A_B2  13120    // 128
#define A_PL  13248    // 128
#define A_MS  13376    // 128 (int)
#define A_VF  13504    // 1
#define A_SMW 13505    // -> 54020 B
// =====================================================================================
__global__ void __launch_bounds__(256, 2)
kA(const float* __restrict__ x, const int* __restrict__ mask,
   const float* __restrict__ b1, const float* __restrict__ b2)
{
    extern __shared__ uint32_t smw[];
    uint32_t* xs  = smw + A_XS;
    uint32_t* w1s = smw + A_W1;
    uint32_t* h1s = smw + A_H1;
    uint32_t* w2s = smw + A_W2;
    float* b1s = (float*)(smw + A_B1);
    float* b2s = (float*)(smw + A_B2);
    float* pl  = (float*)(smw + A_PL);
    int*   ms  = (int*)(smw + A_MS);
    int*   vf  = (int*)(smw + A_VF);

    const int t = threadIdx.x;
    const int lane = t & 31, wid = t >> 5;
    const int g = lane >> 2, tg = lane & 3;
    const int m0 = blockIdx.x * 128;
    const int s  = m0 >> 10;

    // ---- staging ----
    {   // x: 16 floats per thread-half-row -> 8 fp16 pairs
        const int row = t >> 1, half = t & 1;
        const float* gx = x + (size_t)(m0 + row) * 32 + half * 16;
        uint32_t p[8];
        #pragma unroll
        for (int q = 0; q < 4; q++) {
            float4 v = *(const float4*)(gx + 4 * q);
            p[2 * q]     = packh(v.x, v.y);
            p[2 * q + 1] = packh(v.z, v.w);
        }
        *(uint4*)(xs + row * 20 + half * 8)     = make_uint4(p[0], p[1], p[2], p[3]);
        *(uint4*)(xs + row * 20 + half * 8 + 4) = make_uint4(p[4], p[5], p[6], p[7]);
    }
    {   // w1: 1024 words
        const int n = t >> 2, q4 = (t & 3) * 4;
        *(uint4*)(w1s + n * 20 + q4) = *(const uint4*)(g_w1p + n * 16 + q4);
    }
    #pragma unroll
    for (int j = 0; j < 4; j++) {   // w2: 4096 words
        int i = t + j * 256;
        int n = i >> 3, q4 = (i & 7) * 4;
        *(uint4*)(w2s + n * 36 + q4) = *(const uint4*)(g_w2p + n * 32 + q4);
    }
    if (t < 64)  b1s[t] = b1[t];
    if (t < 128) { b2s[t] = b2[t]; pl[t] = 0.f; }
    if (t == 0)  *vf = 0;
    if (t < 128) {
        int mv = (mask[m0 + t] != 0);
        ms[t] = mv;
        if (mv) atomicOr(vf, 1);
    }
    __syncthreads();

    const int wm = (wid & 3) * 32;

    // ---- h1 = relu(x@W1+b1): M128,N64,K32; warp tile 32x32, 2 n-groups ----
    {
        const int wn1 = (wid >> 2) * 32;
        float acc[2][4][4];
        #pragma unroll
        for (int mi = 0; mi < 2; mi++)
            #pragma unroll
            for (int ni = 0; ni < 4; ni++) {
                float ba = b1s[wn1 + ni * 8 + 2 * tg], bb = b1s[wn1 + ni * 8 + 2 * tg + 1];
                acc[mi][ni][0] = ba; acc[mi][ni][1] = bb;
                acc[mi][ni][2] = ba; acc[mi][ni][3] = bb;
            }
        #pragma unroll
        for (int ks = 0; ks < 2; ks++) {
            const int kp0 = ks * 8;
            uint32_t af[2][4];
            #pragma unroll
            for (int mi = 0; mi < 2; mi++) {
                const int R = wm + mi * 16;
                af[mi][0] = xs[(R + g) * 20 + kp0 + tg];
                af[mi][1] = xs[(R + 8 + g) * 20 + kp0 + tg];
                af[mi][2] = xs[(R + g) * 20 + kp0 + tg + 4];
                af[mi][3] = xs[(R + 8 + g) * 20 + kp0 + tg + 4];
            }
            uint32_t bf[4][2];
            #pragma unroll
            for (int ni = 0; ni < 4; ni++) {
                bf[ni][0] = w1s[(wn1 + ni * 8 + g) * 20 + kp0 + tg];
                bf[ni][1] = w1s[(wn1 + ni * 8 + g) * 20 + kp0 + tg + 4];
            }
            #pragma unroll
            for (int mi = 0; mi < 2; mi++)
                #pragma unroll
                for (int ni = 0; ni < 4; ni++) mma_f16(acc[mi][ni], af[mi], bf[ni]);
        }
        #pragma unroll
        for (int mi = 0; mi < 2; mi++) {
            const int R = wm + mi * 16;
            #pragma unroll
            for (int ni = 0; ni < 4; ni++) {
                int kp = wn1 / 2 + ni * 4 + tg;
                h1s[(R + g) * 36 + kp] =
                    packh(fmaxf(acc[mi][ni][0], 0.f), fmaxf(acc[mi][ni][1], 0.f));
                h1s[(R + 8 + g) * 36 + kp] =
                    packh(fmaxf(acc[mi][ni][2], 0.f), fmaxf(acc[mi][ni][3], 0.f));
            }
        }
    }
    __syncthreads();

    // ---- h2 = relu(h1@W2+b2), mask, pool, store: M128,N128,K64; warp tile 32x64 ----
    {
        const int wn2 = (wid >> 2) * 64;
        float acc[2][8][4];
        #pragma unroll
        for (int mi = 0; mi < 2; mi++)
            #pragma unroll
            for (int ni = 0; ni < 8; ni++) {
                float ba = b2s[wn2 + ni * 8 + 2 * tg], bb = b2s[wn2 + ni * 8 + 2 * tg + 1];
                acc[mi][ni][0] = ba; acc[mi][ni][1] = bb;
                acc[mi][ni][2] = ba; acc[mi][ni][3] = bb;
            }
        #pragma unroll
        for (int ks = 0; ks < 4; ks++) {
            const int kp0 = ks * 8;
            uint32_t af[2][4];
            #pragma unroll
            for (int mi = 0; mi < 2; mi++) {
                const int R = wm + mi * 16;
                af[mi][0] = h1s[(R + g) * 36 + kp0 + tg];
                af[mi][1] = h1s[(R + 8 + g) * 36 + kp0 + tg];
                af[mi][2] = h1s[(R + g) * 36 + kp0 + tg + 4];
                af[mi][3] = h1s[(R + 8 + g) * 36 + kp0 + tg + 4];
            }
            uint32_t bf[8][2];
            #pragma unroll
            for (int ni = 0; ni < 8; ni++) {
                bf[ni][0] = w2s[(wn2 + ni * 8 + g) * 36 + kp0 + tg];
                bf[ni][1] = w2s[(wn2 + ni * 8 + g) * 36 + kp0 + tg + 4];
            }
            #pragma unroll
            for (int mi = 0; mi < 2; mi++)
                #pragma unroll
                for (int ni = 0; ni < 8; ni++) mma_f16(acc[mi][ni], af[mi], bf[ni]);
        }
        #pragma unroll
        for (int mi = 0; mi < 2; mi++) {
            const int R = wm + mi * 16;
            const int k0v = ms[R + g], k1v = ms[R + 8 + g];
            #pragma unroll
            for (int ni = 0; ni < 8; ni++) {
                int c0 = wn2 + ni * 8 + 2 * tg;
                int kp = wn2 / 2 + ni * 4 + tg;
                float v0 = k0v ? fmaxf(acc[mi][ni][0], 0.f) : 0.f;
                float v1 = k0v ? fmaxf(acc[mi][ni][1], 0.f) : 0.f;
                float v2 = k1v ? fmaxf(acc[mi][ni][2], 0.f) : 0.f;
                float v3 = k1v ? fmaxf(acc[mi][ni][3], 0.f) : 0.f;
                g_h2p[(size_t)(m0 + R + g) * 64 + kp]     = packh(v0, v1);
                g_h2p[(size_t)(m0 + R + 8 + g) * 64 + kp] = packh(v2, v3);
                atomicMaxF_nonneg(&pl[c0], fmaxf(v0, v2));
                atomicMaxF_nonneg(&pl[c0 + 1], fmaxf(v1, v3));
            }
        }
    }
    __syncthreads();
    if (t < 128) atomicMaxF_nonneg(&g_pool[s * 128 + t], pl[t]);
    if (t == 0 && *vf) atomicOr(&g_valid[s], 1);
}

// ============================= kA2: c = b3 + pool @ W3_bot (fp32) ====================
__global__ void __launch_bounds__(256, 4)
kA2(const float* __restrict__ W3, const float* __restrict__ b3)
{
    __shared__ float ps[128];
    const int t = threadIdx.x, s = blockIdx.x;
    if (t < 128) ps[t] = g_pool[s * 128 + t];
    __syncthreads();
    float acc = b3[t];
    #pragma unroll 8
    for (int k = 0; k < 128; k++)
        acc += ps[k] * W3[(size_t)(128 + k) * D3 + t];
    g_c[s * D3 + t] = acc;
}

// =====================================================================================
// kBC (fp16 MMA): phase1 h3 = relu(h2@W3top + c) (M128,N256,K128) kept in smem as
// fp16 pairs; phase2 acc = h3@W4 in 4 k-chunks (reg-prefetched, single buffer);
// epilogue relu+mask+colmax -> g_feat. 512 threads, warp tiles 32x64 (4m x 4n).
// smem word offsets:
#define BC_R1  0        // 9216 w: h2p [128][68] phase1; W4 chunk [256][36] phase2
#define BC_R2  9216     // 17408 w: w3 [256][68] phase1; h3p [128][132] phase2
#define BC_CV  26624    // 256
#define BC_B4  26880    // 256
#define BC_CM  27136    // 256
#define BC_MS  27392    // 128 (int)
#define BC_SMW 27520    // -> 110080 B
// =====================================================================================
__global__ void __launch_bounds__(512, 1)
kBC(const float* __restrict__ b4, const int* __restrict__ mask)
{
    extern __shared__ uint32_t smw[];
    uint32_t* r1 = smw + BC_R1;
    uint32_t* r2 = smw + BC_R2;
    float* cv   = (float*)(smw + BC_CV);
    float* b4s  = (float*)(smw + BC_B4);
    float* cmax = (float*)(smw + BC_CM);
    int*   ms   = (int*)(smw + BC_MS);

    const int t = threadIdx.x;
    const int lane = t & 31, wid = t >> 5;
    const int g = lane >> 2, tg = lane & 3;
    const int wm = (wid & 3) * 32;
    const int wn = (wid >> 2) * 64;
    const int m0 = blockIdx.x * 128;
    const int s  = m0 >> 10;

    if (t < 256) { cv[t] = g_c[s * D3 + t]; b4s[t] = b4[t]; cmax[t] = 0.f; }
    if (t < 128) ms[t] = (mask[m0 + t] != 0);

    #pragma unroll
    for (int j = 0; j < 4; j++) {      // h2p tile: 8192 words
        int i = t + j * 512;
        int row = i >> 4, q4 = (i & 15) * 4;
        *(uint4*)(r1 + row * 68 + q4) =
            *(const uint4*)(g_h2p + (size_t)(m0 + row) * 64 + q4);
    }
    #pragma unroll
    for (int j = 0; j < 8; j++) {      // w3 packed: 16384 words
        int i = t + j * 512;
        int n = i >> 4, q4 = (i & 15) * 4;
        *(uint4*)(r2 + n * 68 + q4) = *(const uint4*)(g_w3p + n * 64 + q4);
    }
    __syncthreads();

    // ---- phase1: 8 k16-steps ----
    float acc[2][8][4];
    #pragma unroll
    for (int mi = 0; mi < 2; mi++)
        #pragma unroll
        for (int ni = 0; ni < 8; ni++) {
            float ca = cv[wn + ni * 8 + 2 * tg], cb = cv[wn + ni * 8 + 2 * tg + 1];
            acc[mi][ni][0] = ca; acc[mi][ni][1] = cb;
            acc[mi][ni][2] = ca; acc[mi][ni][3] = cb;
        }
    #pragma unroll
    for (int ks = 0; ks < 8; ks++) {
        const int kp0 = ks * 8;
        uint32_t af[2][4];
        #pragma unroll
        for (int mi = 0; mi < 2; mi++) {
            const int R = wm + mi * 16;
            af[mi][0] = r1[(R + g) * 68 + kp0 + tg];
            af[mi][1] = r1[(R + 8 + g) * 68 + kp0 + tg];
            af[mi][2] = r1[(R + g) * 68 + kp0 + tg + 4];
            af[mi][3] = r1[(R + 8 + g) * 68 + kp0 + tg + 4];
        }
        uint32_t bf[8][2];
        #pragma unroll
        for (int ni = 0; ni < 8; ni++) {
            bf[ni][0] = r2[(wn + ni * 8 + g) * 68 + kp0 + tg];
            bf[ni][1] = r2[(wn + ni * 8 + g) * 68 + kp0 + tg + 4];
        }
        #pragma unroll
        for (int mi = 0; mi < 2; mi++)
            #pragma unroll
            for (int ni = 0; ni < 8; ni++) mma_f16(acc[mi][ni], af[mi], bf[ni]);
    }
    __syncthreads();   // all reads of r1/r2 done

    // ---- epilogue1: h3 pairs -> r2; W4 chunk0 -> r1 ----
    #pragma unroll
    for (int mi = 0; mi < 2; mi++) {
        const int R = wm + mi * 16;
        #pragma unroll
        for (int ni = 0; ni < 8; ni++) {
            int kp = wn / 2 + ni * 4 + tg;
            r2[(R + g) * 132 + kp] =
                packh(fmaxf(acc[mi][ni][0], 0.f), fmaxf(acc[mi][ni][1], 0.f));
            r2[(R + 8 + g) * 132 + kp] =
                packh(fmaxf(acc[mi][ni][2], 0.f), fmaxf(acc[mi][ni][3], 0.f));
        }
    }
    #pragma unroll
    for (int j = 0; j < 4; j++) {      // W4 chunk0: 8192 words
        int i = t + j * 512;
        int n = i >> 3, q4 = (i & 7) * 4;
        *(uint4*)(r1 + n * 36 + q4) = *(const uint4*)(g_w4p + n * 128 + q4);
    }
    __syncthreads();

    // ---- phase2: 4 chunks of kp=32 (K=64), single-buffered, reg prefetch ----
    float acc2[2][8][4];
    #pragma unroll
    for (int mi = 0; mi < 2; mi++)
        #pragma unroll
        for (int ni = 0; ni < 8; ni++) {
            float ba = b4s[wn + ni * 8 + 2 * tg], bb = b4s[wn + ni * 8 + 2 * tg + 1];
            acc2[mi][ni][0] = ba; acc2[mi][ni][1] = bb;
            acc2[mi][ni][2] = ba; acc2[mi][ni][3] = bb;
        }
    for (int ch = 0; ch < 4; ++ch) {
        uint4 pre[4];
        if (ch < 3) {
            #pragma unroll
            for (int j = 0; j < 4; j++) {
                int i = t + j * 512;
                int n = i >> 3, q4 = (i & 7) * 4;
                pre[j] = *(const uint4*)(g_w4p + n * 128 + (ch + 1) * 32 + q4);
            }
        }
        #pragma unroll
        for (int ks = 0; ks < 4; ks++) {
            const int kp0 = ks * 8;
            uint32_t af[2][4];
            #pragma unroll
            for (int mi = 0; mi < 2; mi++) {
                const int R = wm + mi * 16;
                af[mi][0] = r2[(R + g) * 132 + ch * 32 + kp0 + tg];
                af[mi][1] = r2[(R + 8 + g) * 132 + ch * 32 + kp0 + tg];
                af[mi][2] = r2[(R + g) * 132 + ch * 32 + kp0 + tg + 4];
                af[mi][3] = r2[(R + 8 + g) * 132 + ch * 32 + kp0 + tg + 4];
            }
            uint32_t bf[8][2];
            #pragma unroll
            for (int ni = 0; ni < 8; ni++) {
                bf[ni][0] = r1[(wn + ni * 8 + g) * 36 + kp0 + tg];
                bf[ni][1] = r1[(wn + ni * 8 + g) * 36 + kp0 + tg + 4];
            }
            #pragma unroll
            for (int mi = 0; mi < 2; mi++)
                #pragma unroll
                for (int ni = 0; ni < 8; ni++) mma_f16(acc2[mi][ni], af[mi], bf[ni]);
        }
        if (ch < 3) {
            __syncthreads();
            #pragma unroll
            for (int j = 0; j < 4; j++) {
                int i = t + j * 512;
                int n = i >> 3, q4 = (i & 7) * 4;
                *(uint4*)(r1 + n * 36 + q4) = pre[j];
            }
            __syncthreads();
        }
    }

    // ---- final epilogue: relu (b4 already in acc), mask rows, col max ----
    #pragma unroll
    for (int ni = 0; ni < 8; ni++) {
        int c0 = wn + ni * 8 + 2 * tg;
        float mx0 = 0.f, mx1 = 0.f;
        #pragma unroll
        for (int mi = 0; mi < 2; mi++) {
            const int R = wm + mi * 16;
            const int k0v = ms[R + g], k1v = ms[R + 8 + g];
            float v0 = fmaxf(acc2[mi][ni][0], 0.f);
            float v1 = fmaxf(acc2[mi][ni][1], 0.f);
            float v2 = fmaxf(acc2[mi][ni][2], 0.f);
            float v3 = fmaxf(acc2[mi][ni][3], 0.f);
            if (k0v) { mx0 = fmaxf(mx0, v0); mx1 = fmaxf(mx1, v1); }
            if (k1v) { mx0 = fmaxf(mx0, v2); mx1 = fmaxf(mx1, v3); }
        }
        atomicMaxF_nonneg(&cmax[c0], mx0);
        atomicMaxF_nonneg(&cmax[c0 + 1], mx1);
    }
    __syncthreads();
    if (t < 256)
        atomicMax((int*)&g_feat[s * D3 + t], __float_as_int(cmax[t]));
}

// ============ kD: out MLP, 8 segments/CTA, weights read once per CTA (fp32) ==========
__global__ void __launch_bounds__(256, 2)
kD(const float* __restrict__ Wo1, const float* __restrict__ bo1,
   const float* __restrict__ Wo2, const float* __restrict__ bo2,
   float* __restrict__ out)
{
    __shared__ float fs[8][256], t1[8][256];
    __shared__ int vld[8];
    const int t = threadIdx.x, s0 = blockIdx.x * 8;
    for (int i = t; i < 8 * 256; i += 256)
        fs[i >> 8][i & 255] = g_feat[(s0 + (i >> 8)) * 256 + (i & 255)];
    if (t < 8) vld[t] = g_valid[s0 + t];
    __syncthreads();
    float a[8];
    #pragma unroll
    for (int e = 0; e < 8; e++) a[e] = bo1[t];
    for (int k = 0; k < 256; k += 4) {
        #pragma unroll
        for (int kk = 0; kk < 4; kk++) {
            float w = Wo1[(k + kk) * 256 + t];
            #pragma unroll
            for (int e = 0; e < 8; e++) a[e] += fs[e][k + kk] * w;
        }
    }
    #pragma unroll
    for (int e = 0; e < 8; e++) t1[e][t] = fmaxf(a[e], 0.f);
    __syncthreads();
    #pragma unroll
    for (int e = 0; e < 8; e++) a[e] = bo2[t];
    for (int k = 0; k < 256; k += 4) {
        #pragma unroll
        for (int kk = 0; kk < 4; kk++) {
            float w = Wo2[(k + kk) * 256 + t];
            #pragma unroll
            for (int e = 0; e < 8; e++) a[e] += t1[e][k + kk] * w;
        }
    }
    #pragma unroll
    for (int e = 0; e < 8; e++)
        out[(s0 + e) * 256 + t] = vld[e] ? a[e] : 0.f;
}

// =====================================================================================
extern "C" void kernel_launch(void* const* d_in, const int* in_sizes, int n_in,
                              void* d_out, int out_size)
{
    (void)in_sizes; (void)n_in; (void)out_size;
    const float* x   = (const float*)d_in[0];
    const int*   msk = (const int*)  d_in[1];
    const float* W1  = (const float*)d_in[2];
    const float* b1  = (const float*)d_in[3];
    const float* W2  = (const float*)d_in[4];
    const float* b2  = (const float*)d_in[5];
    const float* W3  = (const float*)d_in[6];
    const float* b3  = (const float*)d_in[7];
    const float* W4  = (const float*)d_in[8];
    const float* b4  = (const float*)d_in[9];
    const float* Wo1 = (const float*)d_in[10];
    const float* bo1 = (const float*)d_in[11];
    const float* Wo2 = (const float*)d_in[12];
    const float* bo2 = (const float*)d_in[13];
    float* out = (float*)d_out;

    uint32_t *w1p, *w2p, *w3p, *w4p;
    cudaGetSymbolAddress((void**)&w1p, g_w1p);
    cudaGetSymbolAddress((void**)&w2p, g_w2p);
    cudaGetSymbolAddress((void**)&w3p, g_w3p);
    cudaGetSymbolAddress((void**)&w4p, g_w4p);

    const size_t smA  = (size_t)A_SMW * 4;    //  54 KB
    const size_t smBC = (size_t)BC_SMW * 4;   // 107.5 KB

    cudaFuncSetAttribute(kA,  cudaFuncAttributeMaxDynamicSharedMemorySize, (int)smA);
    cudaFuncSetAttribute(kBC, cudaFuncAttributeMaxDynamicSharedMemorySize, (int)smBC);

    kZ<<<S_, 256>>>();
    kP<<<4, 256>>>(W1, w1p, 32, 64);
    kP<<<16, 256>>>(W2, w2p, 64, 128);
    kP<<<64, 256>>>(W3, w3p, 128, 256);    // top half of W3 (rows 0..127)
    kP<<<128, 256>>>(W4, w4p, 256, 256);
    kA <<<NPTS / 128, 256, smA>>>(x, msk, b1, b2);
    kA2<<<S_, 256>>>(W3, b3);
    kBC<<<NPTS / 128, 512, smBC>>>(b4, msk);
    kD <<<64, 256>>>(Wo1, bo1, Wo2, bo2, out);
}

// round 16
// speedup vs baseline: 1.6487x; 1.0036x over previous
#include <cuda_runtime.h>
#include <cstdint>

#define S_  512      // B*T segments
#define P_  1024     // points per segment
#define D3  256
#define NPTS (S_ * P_)

// ---------------- global scratch ----------------
__device__ uint32_t g_h2p[(size_t)NPTS * 64];  // masked h2, packed fp16 pairs (128 MB)
__device__ uint32_t g_w1p[64 * 16];            // W1 packed [n=64][kp=16]
__device__ uint32_t g_w2p[128 * 32];           // W2 packed [n=128][kp=32]
__device__ uint32_t g_w3p[256 * 64];           // W3 top packed [n=256][kp=64]
__device__ uint32_t g_w4p[256 * 128];          // W4 packed [n=256][kp=128]
__device__ float g_pool[S_ * 128];
__device__ float g_c[S_ * D3];
__device__ float g_feat[S_ * D3];
__device__ int   g_valid[S_];

__device__ __forceinline__ void atomicMaxF_nonneg(float* addr, float v) {
    atomicMax((int*)addr, __float_as_int(v));   // valid for non-negative floats
}
__device__ __forceinline__ uint32_t packh(float lo, float hi) {
    uint32_t r; asm("cvt.rn.f16x2.f32 %0, %1, %2;" : "=r"(r) : "f"(hi), "f"(lo)); return r;
}
__device__ __forceinline__ void mma_f16(float d[4], const uint32_t a[4], const uint32_t b[2]) {
    asm volatile(
        "mma.sync.aligned.m16n8k16.row.col.f32.f16.f16.f32 "
        "{%0,%1,%2,%3}, {%4,%5,%6,%7}, {%8,%9}, {%0,%1,%2,%3};\n"
        : "+f"(d[0]), "+f"(d[1]), "+f"(d[2]), "+f"(d[3])
        : "r"(a[0]), "r"(a[1]), "r"(a[2]), "r"(a[3]), "r"(b[0]), "r"(b[1]));
}

// ============================= kZ: zero the accumulators =============================
__global__ void kZ() {
    int i = blockIdx.x * 256 + threadIdx.x;     // grid 512 -> i < 131072
    g_feat[i] = 0.f;
    if (i < S_ * 128) g_pool[i] = 0.f;
    if (i < S_) g_valid[i] = 0;
}

// ============ kP: pack W (K x N f32, row-major) -> dst[n][kp] fp16 pairs ============
__global__ void kP(const float* __restrict__ W, uint32_t* __restrict__ dst, int K, int N) {
    int i = blockIdx.x * 256 + threadIdx.x;
    int total = (K / 2) * N;
    if (i >= total) return;
    int n = i % N, kp = i / N;
    dst[n * (K / 2) + kp] = packh(W[(2 * kp) * N + n], W[(2 * kp + 1) * N + n]);
}

// =====================================================================================
// Kernel A (fp16 MMA): 128 points/CTA, grid 4096, 256 threads.
//   x -> h1(64) -> h2(128) relu+mask, store packed fp16 pairs to g_h2p,
//   col-max -> atomicMax g_pool, valid -> atomicOr g_valid.
//   h1 warp tile 32x32 (full N=64 across 2 n-groups); h2 warp tile 32x64 (full N=128).
// smem word offsets:
#define A_XS  0        // [128][20]  x pairs (kp=16 + 4 pad)
#define A_W1  2560     // [64][20]
#define A_H1  3840     // [128][36]  h1 pairs (kp=32 + 4)
#define A_W2  8448     // [128][36]
#define A_B1  13056    // 64
#define A_B2  13120    // 128
#define A_PL  13248    // 128
#define A_MS  13376    // 128 (int)
#define A_VF  13504    // 1
#define A_SMW 13505    // -> 54020 B
// =====================================================================================
__global__ void __launch_bounds__(256, 2)
kA(const float* __restrict__ x, const int* __restrict__ mask,
   const float* __restrict__ b1, const float* __restrict__ b2)
{
    extern __shared__ uint32_t smw[];
    uint32_t* xs  = smw + A_XS;
    uint32_t* w1s = smw + A_W1;
    uint32_t* h1s = smw + A_H1;
    uint32_t* w2s = smw + A_W2;
    float* b1s = (float*)(smw + A_B1);
    float* b2s = (float*)(smw + A_B2);
    float* pl  = (float*)(smw + A_PL);
    int*   ms  = (int*)(smw + A_MS);
    int*   vf  = (int*)(smw + A_VF);

    const int t = threadIdx.x;
    const int lane = t & 31, wid = t >> 5;
    const int g = lane >> 2, tg = lane & 3;
    const int m0 = blockIdx.x * 128;
    const int s  = m0 >> 10;

    // ---- staging ----
    {   // x: 16 floats per thread-half-row -> 8 fp16 pairs
        const int row = t >> 1, half = t & 1;
        const float* gx = x + (size_t)(m0 + row) * 32 + half * 16;
        uint32_t p[8];
        #pragma unroll
        for (int q = 0; q < 4; q++) {
            float4 v = *(const float4*)(gx + 4 * q);
            p[2 * q]     = packh(v.x, v.y);
            p[2 * q + 1] = packh(v.z, v.w);
        }
        *(uint4*)(xs + row * 20 + half * 8)     = make_uint4(p[0], p[1], p[2], p[3]);
        *(uint4*)(xs + row * 20 + half * 8 + 4) = make_uint4(p[4], p[5], p[6], p[7]);
    }
    {   // w1: 1024 words
        const int n = t >> 2, q4 = (t & 3) * 4;
        *(uint4*)(w1s + n * 20 + q4) = *(const uint4*)(g_w1p + n * 16 + q4);
    }
    #pragma unroll
    for (int j = 0; j < 4; j++) {   // w2: 4096 words
        int i = t + j * 256;
        int n = i >> 3, q4 = (i & 7) * 4;
        *(uint4*)(w2s + n * 36 + q4) = *(const uint4*)(g_w2p + n * 32 + q4);
    }
    if (t < 64)  b1s[t] = b1[t];
    if (t < 128) { b2s[t] = b2[t]; pl[t] = 0.f; }
    if (t == 0)  *vf = 0;
    if (t < 128) {
        int mv = (mask[m0 + t] != 0);
        ms[t] = mv;
        if (mv) atomicOr(vf, 1);
    }
    __syncthreads();

    const int wm = (wid & 3) * 32;

    // ---- h1 = relu(x@W1+b1): M128,N64,K32; warp tile 32x32, 2 n-groups ----
    {
        const int wn1 = (wid >> 2) * 32;
        float acc[2][4][4];
        #pragma unroll
        for (int mi = 0; mi < 2; mi++)
            #pragma unroll
            for (int ni = 0; ni < 4; ni++) {
                float ba = b1s[wn1 + ni * 8 + 2 * tg], bb = b1s[wn1 + ni * 8 + 2 * tg + 1];
                acc[mi][ni][0] = ba; acc[mi][ni][1] = bb;
                acc[mi][ni][2] = ba; acc[mi][ni][3] = bb;
            }
        #pragma unroll
        for (int ks = 0; ks < 2; ks++) {
            const int kp0 = ks * 8;
            uint32_t af[2][4];
            #pragma unroll
            for (int mi = 0; mi < 2; mi++) {
                const int R = wm + mi * 16;
                af[mi][0] = xs[(R + g) * 20 + kp0 + tg];
                af[mi][1] = xs[(R + 8 + g) * 20 + kp0 + tg];
                af[mi][2] = xs[(R + g) * 20 + kp0 + tg + 4];
                af[mi][3] = xs[(R + 8 + g) * 20 + kp0 + tg + 4];
            }
            uint32_t bf[4][2];
            #pragma unroll
            for (int ni = 0; ni < 4; ni++) {
                bf[ni][0] = w1s[(wn1 + ni * 8 + g) * 20 + kp0 + tg];
                bf[ni][1] = w1s[(wn1 + ni * 8 + g) * 20 + kp0 + tg + 4];
            }
            #pragma unroll
            for (int mi = 0; mi < 2; mi++)
                #pragma unroll
                for (int ni = 0; ni < 4; ni++) mma_f16(acc[mi][ni], af[mi], bf[ni]);
        }
        #pragma unroll
        for (int mi = 0; mi < 2; mi++) {
            const int R = wm + mi * 16;
            #pragma unroll
            for (int ni = 0; ni < 4; ni++) {
                int kp = wn1 / 2 + ni * 4 + tg;
                h1s[(R + g) * 36 + kp] =
                    packh(fmaxf(acc[mi][ni][0], 0.f), fmaxf(acc[mi][ni][1], 0.f));
                h1s[(R + 8 + g) * 36 + kp] =
                    packh(fmaxf(acc[mi][ni][2], 0.f), fmaxf(acc[mi][ni][3], 0.f));
            }
        }
    }
    __syncthreads();

    // ---- h2 = relu(h1@W2+b2), mask, pool, store: M128,N128,K64; warp tile 32x64 ----
    {
        const int wn2 = (wid >> 2) * 64;
        float acc[2][8][4];
        #pragma unroll
        for (int mi = 0; mi < 2; mi++)
            #pragma unroll
            for (int ni = 0; ni < 8; ni++) {
                float ba = b2s[wn2 + ni * 8 + 2 * tg], bb = b2s[wn2 + ni * 8 + 2 * tg + 1];
                acc[mi][ni][0] = ba; acc[mi][ni][1] = bb;
                acc[mi][ni][2] = ba; acc[mi][ni][3] = bb;
            }
        #pragma unroll
        for (int ks = 0; ks < 4; ks++) {
            const int kp0 = ks * 8;
            uint32_t af[2][4];
            #pragma unroll
            for (int mi = 0; mi < 2; mi++) {
                const int R = wm + mi * 16;
                af[mi][0] = h1s[(R + g) * 36 + kp0 + tg];
                af[mi][1] = h1s[(R + 8 + g) * 36 + kp0 + tg];
                af[mi][2] = h1s[(R + g) * 36 + kp0 + tg + 4];
                af[mi][3] = h1s[(R + 8 + g) * 36 + kp0 + tg + 4];
            }
            uint32_t bf[8][2];
            #pragma unroll
            for (int ni = 0; ni < 8; ni++) {
                bf[ni][0] = w2s[(wn2 + ni * 8 + g) * 36 + kp0 + tg];
                bf[ni][1] = w2s[(wn2 + ni * 8 + g) * 36 + kp0 + tg + 4];
            }
            #pragma unroll
            for (int mi = 0; mi < 2; mi++)
                #pragma unroll
                for (int ni = 0; ni < 8; ni++) mma_f16(acc[mi][ni], af[mi], bf[ni]);
        }
        #pragma unroll
        for (int mi = 0; mi < 2; mi++) {
            const int R = wm + mi * 16;
            const int k0v = ms[R + g], k1v = ms[R + 8 + g];
            #pragma unroll
            for (int ni = 0; ni < 8; ni++) {
                int c0 = wn2 + ni * 8 + 2 * tg;
                int kp = wn2 / 2 + ni * 4 + tg;
                float v0 = k0v ? fmaxf(acc[mi][ni][0], 0.f) : 0.f;
                float v1 = k0v ? fmaxf(acc[mi][ni][1], 0.f) : 0.f;
                float v2 = k1v ? fmaxf(acc[mi][ni][2], 0.f) : 0.f;
                float v3 = k1v ? fmaxf(acc[mi][ni][3], 0.f) : 0.f;
                g_h2p[(size_t)(m0 + R + g) * 64 + kp]     = packh(v0, v1);
                g_h2p[(size_t)(m0 + R + 8 + g) * 64 + kp] = packh(v2, v3);
                atomicMaxF_nonneg(&pl[c0], fmaxf(v0, v2));
                atomicMaxF_nonneg(&pl[c0 + 1], fmaxf(v1, v3));
            }
        }
    }
    __syncthreads();
    if (t < 128) atomicMaxF_nonneg(&g_pool[s * 128 + t], pl[t]);
    if (t == 0 && *vf) atomicOr(&g_valid[s], 1);
}

// ============================= kA2: c = b3 + pool @ W3_bot (fp32) ====================
__global__ void __launch_bounds__(256, 4)
kA2(const float* __restrict__ W3, const float* __restrict__ b3)
{
    __shared__ float ps[128];
    const int t = threadIdx.x, s = blockIdx.x;
    if (t < 128) ps[t] = g_pool[s * 128 + t];
    __syncthreads();
    float acc = b3[t];
    #pragma unroll 8
    for (int k = 0; k < 128; k++)
        acc += ps[k] * W3[(size_t)(128 + k) * D3 + t];
    g_c[s * D3 + t] = acc;
}

// =====================================================================================
// kBC (fp16 MMA): phase1 h3 = relu(h2@W3top + c) (M128,N256,K128) kept in smem as
// fp16 pairs; phase2 acc = h3@W4 in 4 k-chunks (reg-prefetched, single buffer);
// epilogue relu+mask+colmax -> g_feat. 512 threads, warp tiles 32x64 (4m x 4n).
// smem word offsets:
#define BC_R1  0        // 9216 w: h2p [128][68] phase1; W4 chunk [256][36] phase2
#define BC_R2  9216     // 17408 w: w3 [256][68] phase1; h3p [128][132] phase2
#define BC_CV  26624    // 256
#define BC_B4  26880    // 256
#define BC_CM  27136    // 256
#define BC_MS  27392    // 128 (int)
#define BC_SMW 27520    // -> 110080 B
// =====================================================================================
__global__ void __launch_bounds__(512, 1)
kBC(const float* __restrict__ b4, const int* __restrict__ mask)
{
    extern __shared__ uint32_t smw[];
    uint32_t* r1 = smw + BC_R1;
    uint32_t* r2 = smw + BC_R2;
    float* cv   = (float*)(smw + BC_CV);
    float* b4s  = (float*)(smw + BC_B4);
    float* cmax = (float*)(smw + BC_CM);
    int*   ms   = (int*)(smw + BC_MS);

    const int t = threadIdx.x;
    const int lane = t & 31, wid = t >> 5;
    const int g = lane >> 2, tg = lane & 3;
    const int wm = (wid & 3) * 32;
    const int wn = (wid >> 2) * 64;
    const int m0 = blockIdx.x * 128;
    const int s  = m0 >> 10;

    if (t < 256) { cv[t] = g_c[s * D3 + t]; b4s[t] = b4[t]; cmax[t] = 0.f; }
    if (t < 128) ms[t] = (mask[m0 + t] != 0);

    #pragma unroll
    for (int j = 0; j < 4; j++) {      // h2p tile: 8192 words
        int i = t + j * 512;
        int row = i >> 4, q4 = (i & 15) * 4;
        *(uint4*)(r1 + row * 68 + q4) =
            *(const uint4*)(g_h2p + (size_t)(m0 + row) * 64 + q4);
    }
    #pragma unroll
    for (int j = 0; j < 8; j++) {      // w3 packed: 16384 words
        int i = t + j * 512;
        int n = i >> 4, q4 = (i & 15) * 4;
        *(uint4*)(r2 + n * 68 + q4) = *(const uint4*)(g_w3p + n * 64 + q4);
    }
    __syncthreads();

    // ---- phase1: 8 k16-steps ----
    float acc[2][8][4];
    #pragma unroll
    for (int mi = 0; mi < 2; mi++)
        #pragma unroll
        for (int ni = 0; ni < 8; ni++) {
            float ca = cv[wn + ni * 8 + 2 * tg], cb = cv[wn + ni * 8 + 2 * tg + 1];
            acc[mi][ni][0] = ca; acc[mi][ni][1] = cb;
            acc[mi][ni][2] = ca; acc[mi][ni][3] = cb;
        }
    #pragma unroll
    for (int ks = 0; ks < 8; ks++) {
        const int kp0 = ks * 8;
        uint32_t af[2][4];
        #pragma unroll
        for (int mi = 0; mi < 2; mi++) {
            const int R = wm + mi * 16;
            af[mi][0] = r1[(R + g) * 68 + kp0 + tg];
            af[mi][1] = r1[(R + 8 + g) * 68 + kp0 + tg];
            af[mi][2] = r1[(R + g) * 68 + kp0 + tg + 4];
            af[mi][3] = r1[(R + 8 + g) * 68 + kp0 + tg + 4];
        }
        uint32_t bf[8][2];
        #pragma unroll
        for (int ni = 0; ni < 8; ni++) {
            bf[ni][0] = r2[(wn + ni * 8 + g) * 68 + kp0 + tg];
            bf[ni][1] = r2[(wn + ni * 8 + g) * 68 + kp0 + tg + 4];
        }
        #pragma unroll
        for (int mi = 0; mi < 2; mi++)
            #pragma unroll
            for (int ni = 0; ni < 8; ni++) mma_f16(acc[mi][ni], af[mi], bf[ni]);
    }
    __syncthreads();   // all reads of r1/r2 done

    // ---- epilogue1: h3 pairs -> r2; W4 chunk0 -> r1 ----
    #pragma unroll
    for (int mi = 0; mi < 2; mi++) {
        const int R = wm + mi * 16;
        #pragma unroll
        for (int ni = 0; ni < 8; ni++) {
            int kp = wn / 2 + ni * 4 + tg;
            r2[(R + g) * 132 + kp] =
                packh(fmaxf(acc[mi][ni][0], 0.f), fmaxf(acc[mi][ni][1], 0.f));
            r2[(R + 8 + g) * 132 + kp] =
                packh(fmaxf(acc[mi][ni][2], 0.f), fmaxf(acc[mi][ni][3], 0.f));
        }
    }
    #pragma unroll
    for (int j = 0; j < 4; j++) {      // W4 chunk0: 8192 words
        int i = t + j * 512;
        int n = i >> 3, q4 = (i & 7) * 4;
        *(uint4*)(r1 + n * 36 + q4) = *(const uint4*)(g_w4p + n * 128 + q4);
    }
    __syncthreads();

    // ---- phase2: 4 chunks of kp=32 (K=64), single-buffered, reg prefetch ----
    float acc2[2][8][4];
    #pragma unroll
    for (int mi = 0; mi < 2; mi++)
        #pragma unroll
        for (int ni = 0; ni < 8; ni++) {
            float ba = b4s[wn + ni * 8 + 2 * tg], bb = b4s[wn + ni * 8 + 2 * tg + 1];
            acc2[mi][ni][0] = ba; acc2[mi][ni][1] = bb;
            acc2[mi][ni][2] = ba; acc2[mi][ni][3] = bb;
        }
    for (int ch = 0; ch < 4; ++ch) {
        uint4 pre[4];
        if (ch < 3) {
            #pragma unroll
            for (int j = 0; j < 4; j++) {
                int i = t + j * 512;
                int n = i >> 3, q4 = (i & 7) * 4;
                pre[j] = *(const uint4*)(g_w4p + n * 128 + (ch + 1) * 32 + q4);
            }
        }
        #pragma unroll
        for (int ks = 0; ks < 4; ks++) {
            const int kp0 = ks * 8;
            uint32_t af[2][4];
            #pragma unroll
            for (int mi = 0; mi < 2; mi++) {
                const int R = wm + mi * 16;
                af[mi][0] = r2[(R + g) * 132 + ch * 32 + kp0 + tg];
                af[mi][1] = r2[(R + 8 + g) * 132 + ch * 32 + kp0 + tg];
                af[mi][2] = r2[(R + g) * 132 + ch * 32 + kp0 + tg + 4];
                af[mi][3] = r2[(R + 8 + g) * 132 + ch * 32 + kp0 + tg + 4];
            }
            uint32_t bf[8][2];
            #pragma unroll
            for (int ni = 0; ni < 8; ni++) {
                bf[ni][0] = r1[(wn + ni * 8 + g) * 36 + kp0 + tg];
                bf[ni][1] = r1[(wn + ni * 8 + g) * 36 + kp0 + tg + 4];
            }
            #pragma unroll
            for (int mi = 0; mi < 2; mi++)
                #pragma unroll
                for (int ni = 0; ni < 8; ni++) mma_f16(acc2[mi][ni], af[mi], bf[ni]);
        }
        if (ch < 3) {
            __syncthreads();
            #pragma unroll
            for (int j = 0; j < 4; j++) {
                int i = t + j * 512;
                int n = i >> 3, q4 = (i & 7) * 4;
                *(uint4*)(r1 + n * 36 + q4) = pre[j];
            }
            __syncthreads();
        }
    }

    // ---- final epilogue: relu (b4 already in acc), mask rows, col max ----
    #pragma unroll
    for (int ni = 0; ni < 8; ni++) {
        int c0 = wn + ni * 8 + 2 * tg;
        float mx0 = 0.f, mx1 = 0.f;
        #pragma unroll
        for (int mi = 0; mi < 2; mi++) {
            const int R = wm + mi * 16;
            const int k0v = ms[R + g], k1v = ms[R + 8 + g];
            float v0 = fmaxf(acc2[mi][ni][0], 0.f);
            float v1 = fmaxf(acc2[mi][ni][1], 0.f);
            float v2 = fmaxf(acc2[mi][ni][2], 0.f);
            float v3 = fmaxf(acc2[mi][ni][3], 0.f);
            if (k0v) { mx0 = fmaxf(mx0, v0); mx1 = fmaxf(mx1, v1); }
            if (k1v) { mx0 = fmaxf(mx0, v2); mx1 = fmaxf(mx1, v3); }
        }
        atomicMaxF_nonneg(&cmax[c0], mx0);
        atomicMaxF_nonneg(&cmax[c0 + 1], mx1);
    }
    __syncthreads();
    if (t < 256)
        atomicMax((int*)&g_feat[s * D3 + t], __float_as_int(cmax[t]));
}

// ============ kD: out MLP, 8 segments/CTA, weights read once per CTA (fp32) ==========
__global__ void __launch_bounds__(256, 2)
kD(const float* __restrict__ Wo1, const float* __restrict__ bo1,
   const float* __restrict__ Wo2, const float* __restrict__ bo2,
   float* __restrict__ out)
{
    __shared__ float fs[8][256], t1[8][256];
    __shared__ int vld[8];
    const int t = threadIdx.x, s0 = blockIdx.x * 8;
    for (int i = t; i < 8 * 256; i += 256)
        fs[i >> 8][i & 255] = g_feat[(s0 + (i >> 8)) * 256 + (i & 255)];
    if (t < 8) vld[t] = g_valid[s0 + t];
    __syncthreads();
    float a[8];
    #pragma unroll
    for (int e = 0; e < 8; e++) a[e] = bo1[t];
    for (int k = 0; k < 256; k += 4) {
        #pragma unroll
        for (int kk = 0; kk < 4; kk++) {
            float w = Wo1[(k + kk) * 256 + t];
            #pragma unroll
            for (int e = 0; e < 8; e++) a[e] += fs[e][k + kk] * w;
        }
    }
    #pragma unroll
    for (int e = 0; e < 8; e++) t1[e][t] = fmaxf(a[e], 0.f);
    __syncthreads();
    #pragma unroll
    for (int e = 0; e < 8; e++) a[e] = bo2[t];
    for (int k = 0; k < 256; k += 4) {
        #pragma unroll
        for (int kk = 0; kk < 4; kk++) {
            float w = Wo2[(k + kk) * 256 + t];
            #pragma unroll
            for (int e = 0; e < 8; e++) a[e] += t1[e][k + kk] * w;
        }
    }
    #pragma unroll
    for (int e = 0; e < 8; e++)
        out[(s0 + e) * 256 + t] = vld[e] ? a[e] : 0.f;
}

// =====================================================================================
extern "C" void kernel_launch(void* const* d_in, const int* in_sizes, int n_in,
                              void* d_out, int out_size)
{
    (void)in_sizes; (void)n_in; (void)out_size;
    const float* x   = (const float*)d_in[0];
    const int*   msk = (const int*)  d_in[1];
    const float* W1  = (const float*)d_in[2];
    const float* b1  = (const float*)d_in[3];
    const float* W2  = (const float*)d_in[4];
    const float* b2  = (const float*)d_in[5];
    const float* W3  = (const float*)d_in[6];
    const float* b3  = (const float*)d_in[7];
    const float* W4  = (const float*)d_in[8];
    const float* b4  = (const float*)d_in[9];
    const float* Wo1 = (const float*)d_in[10];
    const float* bo1 = (const float*)d_in[11];
    const float* Wo2 = (const float*)d_in[12];
    const float* bo2 = (const float*)d_in[13];
    float* out = (float*)d_out;

    uint32_t *w1p, *w2p, *w3p, *w4p;
    cudaGetSymbolAddress((void**)&w1p, g_w1p);
    cudaGetSymbolAddress((void**)&w2p, g_w2p);
    cudaGetSymbolAddress((void**)&w3p, g_w3p);
    cudaGetSymbolAddress((void**)&w4p, g_w4p);

    const size_t smA  = (size_t)A_SMW * 4;    //  54 KB
    const size_t smBC = (size_t)BC_SMW * 4;   // 107.5 KB

    cudaFuncSetAttribute(kA,  cudaFuncAttributeMaxDynamicSharedMemorySize, (int)smA);
    cudaFuncSetAttribute(kBC, cudaFuncAttributeMaxDynamicSharedMemorySize, (int)smBC);

    kZ<<<S_, 256>>>();
    kP<<<4, 256>>>(W1, w1p, 32, 64);
    kP<<<16, 256>>>(W2, w2p, 64, 128);
    kP<<<64, 256>>>(W3, w3p, 128, 256);    // top half of W3 (rows 0..127)
    kP<<<128, 256>>>(W4, w4p, 256, 256);
    kA <<<NPTS / 128, 256, smA>>>(x, msk, b1, b2);
    kA2<<<S_, 256>>>(W3, b3);
    kBC<<<NPTS / 128, 512, smBC>>>(b4, msk);
    kD <<<64, 256>>>(Wo1, bo1, Wo2, bo2, out);
}

// round 17
// speedup vs baseline: 1.6502x; 1.0009x over previous
#include <cuda_runtime.h>
#include <cstdint>

#define S_  512      // B*T segments
#define P_  1024     // points per segment
#define D3  256
#define NPTS (S_ * P_)

// ---------------- global scratch ----------------
__device__ uint32_t g_h2p[(size_t)NPTS * 64];  // masked h2, packed fp16 pairs (128 MB)
__device__ uint32_t g_w1p[64 * 16];            // W1 packed [n=64][kp=16]
__device__ uint32_t g_w2p[128 * 32];           // W2 packed [n=128][kp=32]
__device__ uint32_t g_w3p[256 * 64];           // W3 top packed [n=256][kp=64]
__device__ uint32_t g_w4p[256 * 128];          // W4 packed [n=256][kp=128]
__device__ float g_pool[S_ * 128];
__device__ float g_c[S_ * D3];
__device__ float g_feat[S_ * D3];
__device__ int   g_valid[S_];

__device__ __forceinline__ void atomicMaxF_nonneg(float* addr, float v) {
    atomicMax((int*)addr, __float_as_int(v));   // valid for non-negative floats
}
__device__ __forceinline__ uint32_t packh(float lo, float hi) {
    uint32_t r; asm("cvt.rn.f16x2.f32 %0, %1, %2;" : "=r"(r) : "f"(hi), "f"(lo)); return r;
}
__device__ __forceinline__ void mma_f16(float d[4], const uint32_t a[4], const uint32_t b[2]) {
    asm volatile(
        "mma.sync.aligned.m16n8k16.row.col.f32.f16.f16.f32 "
        "{%0,%1,%2,%3}, {%4,%5,%6,%7}, {%8,%9}, {%0,%1,%2,%3};\n"
        : "+f"(d[0]), "+f"(d[1]), "+f"(d[2]), "+f"(d[3])
        : "r"(a[0]), "r"(a[1]), "r"(a[2]), "r"(a[3]), "r"(b[0]), "r"(b[1]));
}

// ============================= kZ: zero the accumulators =============================
__global__ void kZ() {
    int i = blockIdx.x * 256 + threadIdx.x;     // grid 512 -> i < 131072
    g_feat[i] = 0.f;
    if (i < S_ * 128) g_pool[i] = 0.f;
    if (i < S_) g_valid[i] = 0;
}

// ============ kP: pack W (K x N f32, row-major) -> dst[n][kp] fp16 pairs ============
__global__ void kP(const float* __restrict__ W, uint32_t* __restrict__ dst, int K, int N) {
    int i = blockIdx.x * 256 + threadIdx.x;
    int total = (K / 2) * N;
    if (i >= total) return;
    int n = i % N, kp = i / N;
    dst[n * (K / 2) + kp] = packh(W[(2 * kp) * N + n], W[(2 * kp + 1) * N + n]);
}

// =====================================================================================
// Kernel A (fp16 MMA): 128 points/CTA, grid 4096, 256 threads.
//   x -> h1(64) -> h2(128) relu+mask, store packed fp16 pairs to g_h2p,
//   col-max -> atomicMax g_pool, valid -> atomicOr g_valid.
//   h1 warp tile 32x32 (full N=64 across 2 n-groups); h2 warp tile 32x64 (full N=128).
// smem word offsets:
#define A_XS  0        // [128][20]  x pairs (kp=16 + 4 pad)
#define A_W1  2560     // [64][20]
#define A_H1  3840     // [128][36]  h1 pairs (kp=32 + 4)
#define A_W2  8448     // [128][36]
#define A_B1  13056    // 64
#define A_B2  13120    // 128
#define A_PL  13248    // 128
#define A_MS  13376    // 128 (int)
#define A_VF  13504    // 1
#define A_SMW 13505    // -> 54020 B
// =====================================================================================
__global__ void __launch_bounds__(256, 2)
kA(const float* __restrict__ x, const int* __restrict__ mask,
   const float* __restrict__ b1, const float* __restrict__ b2)
{
    extern __shared__ uint32_t smw[];
    uint32_t* xs  = smw + A_XS;
    uint32_t* w1s = smw + A_W1;
    uint32_t* h1s = smw + A_H1;
    uint32_t* w2s = smw + A_W2;
    float* b1s = (float*)(smw + A_B1);
    float* b2s = (float*)(smw + A_B2);
    float* pl  = (float*)(smw + A_PL);
    int*   ms  = (int*)(smw + A_MS);
    int*   vf  = (int*)(smw + A_VF);

    const int t = threadIdx.x;
    const int lane = t & 31, wid = t >> 5;
    const int g = lane >> 2, tg = lane & 3;
    const int m0 = blockIdx.x * 128;
    const int s  = m0 >> 10;

    // ---- staging ----
    {   // x: 16 floats per thread-half-row -> 8 fp16 pairs
        const int row = t >> 1, half = t & 1;
        const float* gx = x + (size_t)(m0 + row) * 32 + half * 16;
        uint32_t p[8];
        #pragma unroll
        for (int q = 0; q < 4; q++) {
            float4 v = *(const float4*)(gx + 4 * q);
            p[2 * q]     = packh(v.x, v.y);
            p[2 * q + 1] = packh(v.z, v.w);
        }
        *(uint4*)(xs + row * 20 + half * 8)     = make_uint4(p[0], p[1], p[2], p[3]);
        *(uint4*)(xs + row * 20 + half * 8 + 4) = make_uint4(p[4], p[5], p[6], p[7]);
    }
    {   // w1: 1024 words
        const int n = t >> 2, q4 = (t & 3) * 4;
        *(uint4*)(w1s + n * 20 + q4) = *(const uint4*)(g_w1p + n * 16 + q4);
    }
    #pragma unroll
    for (int j = 0; j < 4; j++) {   // w2: 4096 words
        int i = t + j * 256;
        int n = i >> 3, q4 = (i & 7) * 4;
        *(uint4*)(w2s + n * 36 + q4) = *(const uint4*)(g_w2p + n * 32 + q4);
    }
    if (t < 64)  b1s[t] = b1[t];
    if (t < 128) { b2s[t] = b2[t]; pl[t] = 0.f; }
    if (t == 0)  *vf = 0;
    if (t < 128) {
        int mv = (mask[m0 + t] != 0);
        ms[t] = mv;
        if (mv) atomicOr(vf, 1);
    }
    __syncthreads();

    const int wm = (wid & 3) * 32;

    // ---- h1 = relu(x@W1+b1): M128,N64,K32; warp tile 32x32, 2 n-groups ----
    {
        const int wn1 = (wid >> 2) * 32;
        float acc[2][4][4];
        #pragma unroll
        for (int mi = 0; mi < 2; mi++)
            #pragma unroll
            for (int ni = 0; ni < 4; ni++) {
                float ba = b1s[wn1 + ni * 8 + 2 * tg], bb = b1s[wn1 + ni * 8 + 2 * tg + 1];
                acc[mi][ni][0] = ba; acc[mi][ni][1] = bb;
                acc[mi][ni][2] = ba; acc[mi][ni][3] = bb;
            }
        #pragma unroll
        for (int ks = 0; ks < 2; ks++) {
            const int kp0 = ks * 8;
            uint32_t af[2][4];
            #pragma unroll
            for (int mi = 0; mi < 2; mi++) {
                const int R = wm + mi * 16;
                af[mi][0] = xs[(R + g) * 20 + kp0 + tg];
                af[mi][1] = xs[(R + 8 + g) * 20 + kp0 + tg];
                af[mi][2] = xs[(R + g) * 20 + kp0 + tg + 4];
                af[mi][3] = xs[(R + 8 + g) * 20 + kp0 + tg + 4];
            }
            uint32_t bf[4][2];
            #pragma unroll
            for (int ni = 0; ni < 4; ni++) {
                bf[ni][0] = w1s[(wn1 + ni * 8 + g) * 20 + kp0 + tg];
                bf[ni][1] = w1s[(wn1 + ni * 8 + g) * 20 + kp0 + tg + 4];
            }
            #pragma unroll
            for (int mi = 0; mi < 2; mi++)
                #pragma unroll
                for (int ni = 0; ni < 4; ni++) mma_f16(acc[mi][ni], af[mi], bf[ni]);
        }
        #pragma unroll
        for (int mi = 0; mi < 2; mi++) {
            const int R = wm + mi * 16;
            #pragma unroll
            for (int ni = 0; ni < 4; ni++) {
                int kp = wn1 / 2 + ni * 4 + tg;
                h1s[(R + g) * 36 + kp] =
                    packh(fmaxf(acc[mi][ni][0], 0.f), fmaxf(acc[mi][ni][1], 0.f));
                h1s[(R + 8 + g) * 36 + kp] =
                    packh(fmaxf(acc[mi][ni][2], 0.f), fmaxf(acc[mi][ni][3], 0.f));
            }
        }
    }
    __syncthreads();

    // ---- h2 = relu(h1@W2+b2), mask, pool, store: M128,N128,K64; warp tile 32x64 ----
    {
        const int wn2 = (wid >> 2) * 64;
        float acc[2][8][4];
        #pragma unroll
        for (int mi = 0; mi < 2; mi++)
            #pragma unroll
            for (int ni = 0; ni < 8; ni++) {
                float ba = b2s[wn2 + ni * 8 + 2 * tg], bb = b2s[wn2 + ni * 8 + 2 * tg + 1];
                acc[mi][ni][0] = ba; acc[mi][ni][1] = bb;
                acc[mi][ni][2] = ba; acc[mi][ni][3] = bb;
            }
        #pragma unroll
        for (int ks = 0; ks < 4; ks++) {
            const int kp0 = ks * 8;
            uint32_t af[2][4];
            #pragma unroll
            for (int mi = 0; mi < 2; mi++) {
                const int R = wm + mi * 16;
                af[mi][0] = h1s[(R + g) * 36 + kp0 + tg];
                af[mi][1] = h1s[(R + 8 + g) * 36 + kp0 + tg];
                af[mi][2] = h1s[(R + g) * 36 + kp0 + tg + 4];
                af[mi][3] = h1s[(R + 8 + g) * 36 + kp0 + tg + 4];
            }
            uint32_t bf[8][2];
            #pragma unroll
            for (int ni = 0; ni < 8; ni++) {
                bf[ni][0] = w2s[(wn2 + ni * 8 + g) * 36 + kp0 + tg];
                bf[ni][1] = w2s[(wn2 + ni * 8 + g) * 36 + kp0 + tg + 4];
            }
            #pragma unroll
            for (int mi = 0; mi < 2; mi++)
                #pragma unroll
                for (int ni = 0; ni < 8; ni++) mma_f16(acc[mi][ni], af[mi], bf[ni]);
        }
        #pragma unroll
        for (int mi = 0; mi < 2; mi++) {
            const int R = wm + mi * 16;
            const int k0v = ms[R + g], k1v = ms[R + 8 + g];
            #pragma unroll
            for (int ni = 0; ni < 8; ni++) {
                int c0 = wn2 + ni * 8 + 2 * tg;
                int kp = wn2 / 2 + ni * 4 + tg;
                float v0 = k0v ? fmaxf(acc[mi][ni][0], 0.f) : 0.f;
                float v1 = k0v ? fmaxf(acc[mi][ni][1], 0.f) : 0.f;
                float v2 = k1v ? fmaxf(acc[mi][ni][2], 0.f) : 0.f;
                float v3 = k1v ? fmaxf(acc[mi][ni][3], 0.f) : 0.f;
                g_h2p[(size_t)(m0 + R + g) * 64 + kp]     = packh(v0, v1);
                g_h2p[(size_t)(m0 + R + 8 + g) * 64 + kp] = packh(v2, v3);
                atomicMaxF_nonneg(&pl[c0], fmaxf(v0, v2));
                atomicMaxF_nonneg(&pl[c0 + 1], fmaxf(v1, v3));
            }
        }
    }
    __syncthreads();
    if (t < 128) atomicMaxF_nonneg(&g_pool[s * 128 + t], pl[t]);
    if (t == 0 && *vf) atomicOr(&g_valid[s], 1);
}

// ============================= kA2: c = b3 + pool @ W3_bot (fp32) ====================
__global__ void __launch_bounds__(256, 4)
kA2(const float* __restrict__ W3, const float* __restrict__ b3)
{
    __shared__ float ps[128];
    const int t = threadIdx.x, s = blockIdx.x;
    if (t < 128) ps[t] = g_pool[s * 128 + t];
    __syncthreads();
    float acc = b3[t];
    #pragma unroll 8
    for (int k = 0; k < 128; k++)
        acc += ps[k] * W3[(size_t)(128 + k) * D3 + t];
    g_c[s * D3 + t] = acc;
}

// =====================================================================================
// kBC (fp16 MMA): phase1 h3 = relu(h2@W3top + c) (M128,N256,K128) kept in smem as
// fp16 pairs; phase2 acc = h3@W4 in 4 k-chunks (reg-prefetched, single buffer);
// epilogue relu+mask+colmax -> g_feat. 512 threads, warp tiles 32x64 (4m x 4n).
// smem word offsets:
#define BC_R1  0        // 9216 w: h2p [128][68] phase1; W4 chunk [256][36] phase2
#define BC_R2  9216     // 17408 w: w3 [256][68] phase1; h3p [128][132] phase2
#define BC_CV  26624    // 256
#define BC_B4  26880    // 256
#define BC_CM  27136    // 256
#define BC_MS  27392    // 128 (int)
#define BC_SMW 27520    // -> 110080 B
// =====================================================================================
__global__ void __launch_bounds__(512, 1)
kBC(const float* __restrict__ b4, const int* __restrict__ mask)
{
    extern __shared__ uint32_t smw[];
    uint32_t* r1 = smw + BC_R1;
    uint32_t* r2 = smw + BC_R2;
    float* cv   = (float*)(smw + BC_CV);
    float* b4s  = (float*)(smw + BC_B4);
    float* cmax = (float*)(smw + BC_CM);
    int*   ms   = (int*)(smw + BC_MS);

    const int t = threadIdx.x;
    const int lane = t & 31, wid = t >> 5;
    const int g = lane >> 2, tg = lane & 3;
    const int wm = (wid & 3) * 32;
    const int wn = (wid >> 2) * 64;
    const int m0 = blockIdx.x * 128;
    const int s  = m0 >> 10;

    if (t < 256) { cv[t] = g_c[s * D3 + t]; b4s[t] = b4[t]; cmax[t] = 0.f; }
    if (t < 128) ms[t] = (mask[m0 + t] != 0);

    #pragma unroll
    for (int j = 0; j < 4; j++) {      // h2p tile: 8192 words
        int i = t + j * 512;
        int row = i >> 4, q4 = (i & 15) * 4;
        *(uint4*)(r1 + row * 68 + q4) =
            *(const uint4*)(g_h2p + (size_t)(m0 + row) * 64 + q4);
    }
    #pragma unroll
    for (int j = 0; j < 8; j++) {      // w3 packed: 16384 words
        int i = t + j * 512;
        int n = i >> 4, q4 = (i & 15) * 4;
        *(uint4*)(r2 + n * 68 + q4) = *(const uint4*)(g_w3p + n * 64 + q4);
    }
    __syncthreads();

    // ---- phase1: 8 k16-steps ----
    float acc[2][8][4];
    #pragma unroll
    for (int mi = 0; mi < 2; mi++)
        #pragma unroll
        for (int ni = 0; ni < 8; ni++) {
            float ca = cv[wn + ni * 8 + 2 * tg], cb = cv[wn + ni * 8 + 2 * tg + 1];
            acc[mi][ni][0] = ca; acc[mi][ni][1] = cb;
            acc[mi][ni][2] = ca; acc[mi][ni][3] = cb;
        }
    #pragma unroll
    for (int ks = 0; ks < 8; ks++) {
        const int kp0 = ks * 8;
        uint32_t af[2][4];
        #pragma unroll
        for (int mi = 0; mi < 2; mi++) {
            const int R = wm + mi * 16;
            af[mi][0] = r1[(R + g) * 68 + kp0 + tg];
            af[mi][1] = r1[(R + 8 + g) * 68 + kp0 + tg];
            af[mi][2] = r1[(R + g) * 68 + kp0 + tg + 4];
            af[mi][3] = r1[(R + 8 + g) * 68 + kp0 + tg + 4];
        }
        uint32_t bf[8][2];
        #pragma unroll
        for (int ni = 0; ni < 8; ni++) {
            bf[ni][0] = r2[(wn + ni * 8 + g) * 68 + kp0 + tg];
            bf[ni][1] = r2[(wn + ni * 8 + g) * 68 + kp0 + tg + 4];
        }
        #pragma unroll
        for (int mi = 0; mi < 2; mi++)
            #pragma unroll
            for (int ni = 0; ni < 8; ni++) mma_f16(acc[mi][ni], af[mi], bf[ni]);
    }
    __syncthreads();   // all reads of r1/r2 done

    // ---- epilogue1: h3 pairs -> r2; W4 chunk0 -> r1 ----
    #pragma unroll
    for (int mi = 0; mi < 2; mi++) {
        const int R = wm + mi * 16;
        #pragma unroll
        for (int ni = 0; ni < 8; ni++) {
            int kp = wn / 2 + ni * 4 + tg;
            r2[(R + g) * 132 + kp] =
                packh(fmaxf(acc[mi][ni][0], 0.f), fmaxf(acc[mi][ni][1], 0.f));
            r2[(R + 8 + g) * 132 + kp] =
                packh(fmaxf(acc[mi][ni][2], 0.f), fmaxf(acc[mi][ni][3], 0.f));
        }
    }
    #pragma unroll
    for (int j = 0; j < 4; j++) {      // W4 chunk0: 8192 words
        int i = t + j * 512;
        int n = i >> 3, q4 = (i & 7) * 4;
        *(uint4*)(r1 + n * 36 + q4) = *(const uint4*)(g_w4p + n * 128 + q4);
    }
    __syncthreads();

    // ---- phase2: 4 chunks of kp=32 (K=64), single-buffered, reg prefetch ----
    float acc2[2][8][4];
    #pragma unroll
    for (int mi = 0; mi < 2; mi++)
        #pragma unroll
        for (int ni = 0; ni < 8; ni++) {
            float ba = b4s[wn + ni * 8 + 2 * tg], bb = b4s[wn + ni * 8 + 2 * tg + 1];
            acc2[mi][ni][0] = ba; acc2[mi][ni][1] = bb;
            acc2[mi][ni][2] = ba; acc2[mi][ni][3] = bb;
        }
    for (int ch = 0; ch < 4; ++ch) {
        uint4 pre[4];
        if (ch < 3) {
            #pragma unroll
            for (int j = 0; j < 4; j++) {
                int i = t + j * 512;
                int n = i >> 3, q4 = (i & 7) * 4;
                pre[j] = *(const uint4*)(g_w4p + n * 128 + (ch + 1) * 32 + q4);
            }
        }
        #pragma unroll
        for (int ks = 0; ks < 4; ks++) {
            const int kp0 = ks * 8;
            uint32_t af[2][4];
            #pragma unroll
            for (int mi = 0; mi < 2; mi++) {
                const int R = wm + mi * 16;
                af[mi][0] = r2[(R + g) * 132 + ch * 32 + kp0 + tg];
                af[mi][1] = r2[(R + 8 + g) * 132 + ch * 32 + kp0 + tg];
                af[mi][2] = r2[(R + g) * 132 + ch * 32 + kp0 + tg + 4];
                af[mi][3] = r2[(R + 8 + g) * 132 + ch * 32 + kp0 + tg + 4];
            }
            uint32_t bf[8][2];
            #pragma unroll
            for (int ni = 0; ni < 8; ni++) {
                bf[ni][0] = r1[(wn + ni * 8 + g) * 36 + kp0 + tg];
                bf[ni][1] = r1[(wn + ni * 8 + g) * 36 + kp0 + tg + 4];
            }
            #pragma unroll
            for (int mi = 0; mi < 2; mi++)
                #pragma unroll
                for (int ni = 0; ni < 8; ni++) mma_f16(acc2[mi][ni], af[mi], bf[ni]);
        }
        if (ch < 3) {
            __syncthreads();
            #pragma unroll
            for (int j = 0; j < 4; j++) {
                int i = t + j * 512;
                int n = i >> 3, q4 = (i & 7) * 4;
                *(uint4*)(r1 + n * 36 + q4) = pre[j];
            }
            __syncthreads();
        }
    }

    // ---- final epilogue: relu (b4 already in acc), mask rows, col max ----
    #pragma unroll
    for (int ni = 0; ni < 8; ni++) {
        int c0 = wn + ni * 8 + 2 * tg;
        float mx0 = 0.f, mx1 = 0.f;
        #pragma unroll
        for (int mi = 0; mi < 2; mi++) {
            const int R = wm + mi * 16;
            const int k0v = ms[R + g], k1v = ms[R + 8 + g];
            float v0 = fmaxf(acc2[mi][ni][0], 0.f);
            float v1 = fmaxf(acc2[mi][ni][1], 0.f);
            float v2 = fmaxf(acc2[mi][ni][2], 0.f);
            float v3 = fmaxf(acc2[mi][ni][3], 0.f);
            if (k0v) { mx0 = fmaxf(mx0, v0); mx1 = fmaxf(mx1, v1); }
            if (k1v) { mx0 = fmaxf(mx0, v2); mx1 = fmaxf(mx1, v3); }
        }
        atomicMaxF_nonneg(&cmax[c0], mx0);
        atomicMaxF_nonneg(&cmax[c0 + 1], mx1);
    }
    __syncthreads();
    if (t < 256)
        atomicMax((int*)&g_feat[s * D3 + t], __float_as_int(cmax[t]));
}

// ============ kD: out MLP, 8 segments/CTA, weights read once per CTA (fp32) ==========
__global__ void __launch_bounds__(256, 2)
kD(const float* __restrict__ Wo1, const float* __restrict__ bo1,
   const float* __restrict__ Wo2, const float* __restrict__ bo2,
   float* __restrict__ out)
{
    __shared__ float fs[8][256], t1[8][256];
    __shared__ int vld[8];
    const int t = threadIdx.x, s0 = blockIdx.x * 8;
    for (int i = t; i < 8 * 256; i += 256)
        fs[i >> 8][i & 255] = g_feat[(s0 + (i >> 8)) * 256 + (i & 255)];
    if (t < 8) vld[t] = g_valid[s0 + t];
    __syncthreads();
    float a[8];
    #pragma unroll
    for (int e = 0; e < 8; e++) a[e] = bo1[t];
    for (int k = 0; k < 256; k += 4) {
        #pragma unroll
        for (int kk = 0; kk < 4; kk++) {
            float w = Wo1[(k + kk) * 256 + t];
            #pragma unroll
            for (int e = 0; e < 8; e++) a[e] += fs[e][k + kk] * w;
        }
    }
    #pragma unroll
    for (int e = 0; e < 8; e++) t1[e][t] = fmaxf(a[e], 0.f);
    __syncthreads();
    #pragma unroll
    for (int e = 0; e < 8; e++) a[e] = bo2[t];
    for (int k = 0; k < 256; k += 4) {
        #pragma unroll
        for (int kk = 0; kk < 4; kk++) {
            float w = Wo2[(k + kk) * 256 + t];
            #pragma unroll
            for (int e = 0; e < 8; e++) a[e] += t1[e][k + kk] * w;
        }
    }
    #pragma unroll
    for (int e = 0; e < 8; e++)
        out[(s0 + e) * 256 + t] = vld[e] ? a[e] : 0.f;
}

// =====================================================================================
extern "C" void kernel_launch(void* const* d_in, const int* in_sizes, int n_in,
                              void* d_out, int out_size)
{
    (void)in_sizes; (void)n_in; (void)out_size;
    const float* x   = (const float*)d_in[0];
    const int*   msk = (const int*)  d_in[1];
    const float* W1  = (const float*)d_in[2];
    const float* b1  = (const float*)d_in[3];
    const float* W2  = (const float*)d_in[4];
    const float* b2  = (const float*)d_in[5];
    const float* W3  = (const float*)d_in[6];
    const float* b3  = (const float*)d_in[7];
    const float* W4  = (const float*)d_in[8];
    const float* b4  = (const float*)d_in[9];
    const float* Wo1 = (const float*)d_in[10];
    const float* bo1 = (const float*)d_in[11];
    const float* Wo2 = (const float*)d_in[12];
    const float* bo2 = (const float*)d_in[13];
    float* out = (float*)d_out;

    uint32_t *w1p, *w2p, *w3p, *w4p;
    cudaGetSymbolAddress((void**)&w1p, g_w1p);
    cudaGetSymbolAddress((void**)&w2p, g_w2p);
    cudaGetSymbolAddress((void**)&w3p, g_w3p);
    cudaGetSymbolAddress((void**)&w4p, g_w4p);

    const size_t smA  = (size_t)A_SMW * 4;    //  54 KB
    const size_t smBC = (size_t)BC_SMW * 4;   // 107.5 KB

    cudaFuncSetAttribute(kA,  cudaFuncAttributeMaxDynamicSharedMemorySize, (int)smA);
    cudaFuncSetAttribute(kBC, cudaFuncAttributeMaxDynamicSharedMemorySize, (int)smBC);

    kZ<<<S_, 256>>>();
    kP<<<4, 256>>>(W1, w1p, 32, 64);
    kP<<<16, 256>>>(W2, w2p, 64, 128);
    kP<<<64, 256>>>(W3, w3p, 128, 256);    // top half of W3 (rows 0..127)
    kP<<<128, 256>>>(W4, w4p, 256, 256);
    kA <<<NPTS / 128, 256, smA>>>(x, msk, b1, b2);
    kA2<<<S_, 256>>>(W3, b3);
    kBC<<<NPTS / 128, 512, smBC>>>(b4, msk);
    kD <<<64, 256>>>(Wo1, bo1, Wo2, bo2, out);
}